// round 1
// baseline (speedup 1.0000x reference)
#include <cuda_runtime.h>
#include <math.h>

#define NB   2048          // batch
#define NT   64            // timesteps
#define NL   8             // lanes
#define NH   64            // hidden
#define NSEQ (NB*NL)       // 16384 GRU sequences
#define SPB  8             // sequences per GRU block
#define GRU_THREADS 192    // 3 gates * 64 hidden units

// scratch (allocations are forbidden; __device__ globals are allowed)
__device__ float g_x[NSEQ * NT * 4];      // GRU inputs, [seq][t][4]
__device__ float g_hidden[NSEQ * NH];     // final hidden, [seq][h]

__device__ __forceinline__ float sigf(float x) {
    return 1.0f / (1.0f + __expf(-x));
}

// ---------------------------------------------------------------------------
// Kernel 1: history gather + (3->4) matmul + sigmoid  =>  g_x
// ---------------------------------------------------------------------------
__global__ void prep_kernel(const float* __restrict__ hist,
                            const float* __restrict__ Wh,
                            const float* __restrict__ bh)
{
    int idx = blockIdx.x * blockDim.x + threadIdx.x;   // over B*T*8
    if (idx >= NB * NT * NL) return;
    int l = idx & 7;
    int t = (idx >> 3) & 63;
    int b = idx >> 9;

    const float* hp = hist + (b * NT + t) * 24;
    float h0 = hp[l];
    float h1 = hp[l + 8];
    float h2 = hp[l + 16];

    float* xp = g_x + ((b * NL + l) * NT + t) * 4;
#pragma unroll
    for (int o = 0; o < 4; o++) {
        float v = bh[o] + Wh[o*3 + 0] * h0 + Wh[o*3 + 1] * h1 + Wh[o*3 + 2] * h2;
        xp[o] = sigf(v);
    }
}

// ---------------------------------------------------------------------------
// Kernel 2: GRU over 64 steps.
// Block = 192 threads; thread t owns row t of Whh (gate g = t/64, unit j = t%64),
// row cached in registers. Each block advances SPB=8 sequences.
// ---------------------------------------------------------------------------
__global__ __launch_bounds__(GRU_THREADS, 3)
void gru_kernel(const float* __restrict__ Wih,
                const float* __restrict__ Whh,
                const float* __restrict__ bih,
                const float* __restrict__ bhh)
{
    __shared__ float sh_x[SPB][NT * 4];        // 8 KB
    __shared__ float sh_h[SPB][NH];            // 2 KB
    __shared__ float sh_pre[4][SPB][NH];       // 8 KB: pre_r, pre_z, gi_n, gh_n

    const int t = threadIdx.x;
    const int g = t >> 6;          // 0=r, 1=z, 2=n
    const int j = t & 63;
    const int seq0 = blockIdx.x * SPB;

    // cache this thread's Whh row + Wih row + biases in registers
    float w[NH];
#pragma unroll
    for (int k = 0; k < NH; k++) w[k] = Whh[t * NH + k];
    const float wi0 = Wih[t*4 + 0], wi1 = Wih[t*4 + 1];
    const float wi2 = Wih[t*4 + 2], wi3 = Wih[t*4 + 3];
    const float b_i = bih[t], b_h = bhh[t];

    // stage all x for this block's sequences (contiguous: g_x[seq0*256 ...])
    for (int idx = t; idx < SPB * NT * 4; idx += GRU_THREADS)
        sh_x[idx >> 8][idx & 255] = g_x[seq0 * (NT*4) + idx];
    for (int idx = t; idx < SPB * NH; idx += GRU_THREADS)
        sh_h[idx >> 6][idx & 63] = 0.0f;
    __syncthreads();

    for (int step = 0; step < NT; step++) {
        // ---- phase 1: gate pre-activations (matvec vs h, + input part) ----
        float acc[SPB];
#pragma unroll
        for (int s = 0; s < SPB; s++) acc[s] = 0.0f;

#pragma unroll
        for (int k4 = 0; k4 < NH / 4; k4++) {
#pragma unroll
            for (int s = 0; s < SPB; s++) {
                float4 h4 = *reinterpret_cast<const float4*>(&sh_h[s][k4 * 4]);
                acc[s] = fmaf(w[k4*4 + 0], h4.x, acc[s]);
                acc[s] = fmaf(w[k4*4 + 1], h4.y, acc[s]);
                acc[s] = fmaf(w[k4*4 + 2], h4.z, acc[s]);
                acc[s] = fmaf(w[k4*4 + 3], h4.w, acc[s]);
            }
        }

#pragma unroll
        for (int s = 0; s < SPB; s++) {
            const float* xs = &sh_x[s][step * 4];
            float gi = b_i + wi0 * xs[0] + wi1 * xs[1] + wi2 * xs[2] + wi3 * xs[3];
            float gh = b_h + acc[s];
            if (g < 2) {
                sh_pre[g][s][j] = gi + gh;
            } else {
                sh_pre[2][s][j] = gi;
                sh_pre[3][s][j] = gh;
            }
        }
        __syncthreads();

        // ---- phase 2: gate nonlinearity + hidden update ----
        for (int idx = t; idx < SPB * NH; idx += GRU_THREADS) {
            int s = idx >> 6, jj = idx & 63;
            float r    = sigf(sh_pre[0][s][jj]);
            float z    = sigf(sh_pre[1][s][jj]);
            float cand = tanhf(fmaf(r, sh_pre[3][s][jj], sh_pre[2][s][jj]));
            float hp   = sh_h[s][jj];
            sh_h[s][jj] = (1.0f - z) * cand + z * hp;
        }
        __syncthreads();
    }

    for (int idx = t; idx < SPB * NH; idx += GRU_THREADS)
        g_hidden[seq0 * NH + idx] = sh_h[idx >> 6][idx & 63];
}

// ---------------------------------------------------------------------------
// Kernel 3: lane MLP + phase competition head. One block per batch element.
// ---------------------------------------------------------------------------
__constant__ int c_PL[8][2] = {{1,3},{0,2},{5,7},{4,6},{0,1},{2,3},{4,5},{6,7}};

__global__ __launch_bounds__(64)
void post_kernel(const float* __restrict__ feat,
                 const int*   __restrict__ relation,
                 const float* __restrict__ emb_phase,
                 const float* __restrict__ Wv,  const float* __restrict__ bv,
                 const float* __restrict__ Wl,  const float* __restrict__ bl,
                 const float* __restrict__ emb_const,
                 const float* __restrict__ Wcf, const float* __restrict__ bcf,
                 const float* __restrict__ Wcc, const float* __restrict__ bcc,
                 const float* __restrict__ Wcm, const float* __restrict__ bcm,
                 const float* __restrict__ Wfin,const float* __restrict__ bfin,
                 float* __restrict__ out)
{
    __shared__ float s_hid[NL][NH];        // 2 KB
    __shared__ float s_lf[NL][8];          // veh(4) + ph(4)
    __shared__ float s_line[NL][16];
    __shared__ float s_pp[NL][16];
    __shared__ float s_Wl[16 * 72];        // 4.5 KB
    __shared__ float s_yc[NL][7][20];      // 4.4 KB
    __shared__ float s_val[NL][7];

    const int tid = threadIdx.x;
    const int b = blockIdx.x;

    for (int i = tid; i < NL * NH; i += 64)
        s_hid[i >> 6][i & 63] = g_hidden[b * (NL * NH) + i];
    for (int i = tid; i < 16 * 72; i += 64)
        s_Wl[i] = Wl[i];

    // veh + ph (64 values)
    {
        int l = tid >> 3, c4 = tid & 7;
        if (c4 < 4) {
            float vr = feat[b * 16 + 8 + l];
            s_lf[l][c4] = sigf(fmaf(vr, Wv[c4], bv[c4]));
        } else {
            int c = c4 - 4;
            int pid = (int)feat[b * 16 + l];
            s_lf[l][c4] = sigf(emb_phase[pid * 4 + c]);
        }
    }

    // yc (constant per (p,q)): relu(emb_const[relation] @ Wcc^T + bcc)
    for (int i = tid; i < NL * 7 * 20; i += 64) {
        int o = i % 20, pq = i / 20;
        int p = pq / 7, q = pq % 7;
        const float* ce = emb_const + relation[p * 7 + q] * 4;
        float v = bcc[o];
#pragma unroll
        for (int c = 0; c < 4; c++) v = fmaf(ce[c], Wcc[o * 4 + c], v);
        s_yc[p][q][o] = fmaxf(v, 0.0f);
    }
    __syncthreads();

    // line = relu(lane_feat @ Wl^T + bl)  (128 outputs)
    for (int i = tid; i < NL * 16; i += 64) {
        int l = i >> 4, o = i & 15;
        const float* wrow = &s_Wl[o * 72];
        float v = bl[o];
#pragma unroll
        for (int c = 0; c < 8; c++)  v = fmaf(s_lf[l][c], wrow[c], v);
#pragma unroll
        for (int k = 0; k < NH; k++) v = fmaf(s_hid[l][k], wrow[8 + k], v);
        s_line[l][o] = fmaxf(v, 0.0f);
    }
    __syncthreads();

    // pp[p] = line[PL[p][0]] + line[PL[p][1]]
    for (int i = tid; i < NL * 16; i += 64) {
        int p = i >> 4, o = i & 15;
        s_pp[p][o] = s_line[c_PL[p][0]][o] + s_line[c_PL[p][1]][o];
    }
    __syncthreads();

    // per-(p,q) competition MLP (56 pairs -> threads 0..55)
    if (tid < 56) {
        int p = tid / 7, qi = tid % 7;
        int jq = (qi < p) ? qi : qi + 1;

        float xf[20];
#pragma unroll
        for (int o = 0; o < 20; o++) {
            const float* wc = Wcf + o * 32;
            float v = bcf[o];
#pragma unroll
            for (int c = 0; c < 16; c++) v = fmaf(s_pp[p][c],  wc[c],      v);
#pragma unroll
            for (int c = 0; c < 16; c++) v = fmaf(s_pp[jq][c], wc[16 + c], v);
            xf[o] = fmaxf(v, 0.0f) * s_yc[p][qi][o];
        }
        float val = bfin[0];
#pragma unroll
        for (int o = 0; o < 20; o++) {
            const float* wm = Wcm + o * 20;
            float v = bcm[o];
#pragma unroll
            for (int c = 0; c < 20; c++) v = fmaf(xf[c], wm[c], v);
            val = fmaf(fmaxf(v, 0.0f), Wfin[o], val);
        }
        s_val[p][qi] = val;
    }
    __syncthreads();

    if (tid < NL) {
        float acc = 0.0f;
#pragma unroll
        for (int q = 0; q < 7; q++) acc += s_val[tid][q];
        out[b * NL + tid] = acc;
    }
}

// ---------------------------------------------------------------------------
// Launch
// ---------------------------------------------------------------------------
extern "C" void kernel_launch(void* const* d_in, const int* in_sizes, int n_in,
                              void* d_out, int out_size)
{
    const float* feature  = (const float*)d_in[0];
    const float* history  = (const float*)d_in[1];
    const int*   relation = (const int*)  d_in[2];
    const float* emb_phase= (const float*)d_in[3];
    const float* Wv       = (const float*)d_in[4];
    const float* bv       = (const float*)d_in[5];
    const float* Wh       = (const float*)d_in[6];
    const float* bh       = (const float*)d_in[7];
    const float* Wih      = (const float*)d_in[8];
    const float* Whh      = (const float*)d_in[9];
    const float* bih      = (const float*)d_in[10];
    const float* bhh      = (const float*)d_in[11];
    const float* Wl       = (const float*)d_in[12];
    const float* bl       = (const float*)d_in[13];
    const float* emb_const= (const float*)d_in[14];
    const float* Wcf      = (const float*)d_in[15];
    const float* bcf      = (const float*)d_in[16];
    const float* Wcc      = (const float*)d_in[17];
    const float* bcc      = (const float*)d_in[18];
    const float* Wcm      = (const float*)d_in[19];
    const float* bcm      = (const float*)d_in[20];
    const float* Wfin     = (const float*)d_in[21];
    const float* bfin     = (const float*)d_in[22];
    float* out = (float*)d_out;

    {
        int total = NB * NT * NL;
        int threads = 256;
        prep_kernel<<<(total + threads - 1) / threads, threads>>>(history, Wh, bh);
    }
    gru_kernel<<<NSEQ / SPB, GRU_THREADS>>>(Wih, Whh, bih, bhh);
    post_kernel<<<NB, 64>>>(feature, relation, emb_phase, Wv, bv, Wl, bl,
                            emb_const, Wcf, bcf, Wcc, bcc, Wcm, bcm,
                            Wfin, bfin, out);
}

// round 2
// speedup vs baseline: 1.0115x; 1.0115x over previous
#include <cuda_runtime.h>
#include <math.h>

#define NB   2048          // batch
#define NT   64            // timesteps
#define NL   8             // lanes
#define NH   64            // hidden
#define NSEQ (NB*NL)       // 16384 GRU sequences
#define SPB  8             // sequences per GRU block
#define GRU_THREADS 192    // 3 gates * 64 hidden units

// scratch (allocations are forbidden; __device__ globals are allowed)
__device__ float g_x[NSEQ * NT * 4];      // GRU inputs, [seq][t][4]
__device__ float g_hidden[NSEQ * NH];     // final hidden, [seq][h]

__device__ __forceinline__ float sigf(float x) {
    return 1.0f / (1.0f + __expf(-x));
}

// ---- packed f32x2 helpers (Blackwell FFMA2 — ptxas never emits this from C++) ----
__device__ __forceinline__ unsigned long long pack2(float lo, float hi) {
    unsigned long long r;
    asm("mov.b64 %0, {%1, %2};" : "=l"(r) : "f"(lo), "f"(hi));
    return r;
}
__device__ __forceinline__ void fma2(unsigned long long& d,
                                     unsigned long long a,
                                     unsigned long long b) {
    asm("fma.rn.f32x2 %0, %1, %2, %3;" : "=l"(d) : "l"(a), "l"(b), "l"(d));
}
__device__ __forceinline__ float2 unpack2(unsigned long long v) {
    float2 f;
    asm("mov.b64 {%0, %1}, %2;" : "=f"(f.x), "=f"(f.y) : "l"(v));
    return f;
}

// ---------------------------------------------------------------------------
// Kernel 1: history gather + (3->4) matmul + sigmoid  =>  g_x
// ---------------------------------------------------------------------------
__global__ void prep_kernel(const float* __restrict__ hist,
                            const float* __restrict__ Wh,
                            const float* __restrict__ bh)
{
    int idx = blockIdx.x * blockDim.x + threadIdx.x;   // over B*T*8
    if (idx >= NB * NT * NL) return;
    int l = idx & 7;
    int t = (idx >> 3) & 63;
    int b = idx >> 9;

    const float* hp = hist + (b * NT + t) * 24;
    float h0 = hp[l];
    float h1 = hp[l + 8];
    float h2 = hp[l + 16];

    float* xp = g_x + ((b * NL + l) * NT + t) * 4;
#pragma unroll
    for (int o = 0; o < 4; o++) {
        float v = bh[o] + Wh[o*3 + 0] * h0 + Wh[o*3 + 1] * h1 + Wh[o*3 + 2] * h2;
        xp[o] = sigf(v);
    }
}

// ---------------------------------------------------------------------------
// Kernel 2: GRU over 64 steps, FFMA2 mainloop.
// Block = 192 threads; thread t owns row t of Whh (gate g = t/64, unit j = t%64),
// row cached as 32 packed f32x2 values. Each block advances SPB=8 sequences.
// ---------------------------------------------------------------------------
__global__ __launch_bounds__(GRU_THREADS, 3)
void gru_kernel(const float* __restrict__ Wih,
                const float* __restrict__ Whh,
                const float* __restrict__ bih,
                const float* __restrict__ bhh)
{
    __shared__ float sh_x[SPB][NT * 4];        // 8 KB
    __shared__ float sh_h[SPB][NH];            // 2 KB (rows 256B -> 16B aligned)
    __shared__ float sh_pre[4][SPB][NH];       // 8 KB: pre_r, pre_z, gi_n, gh_n

    const int t = threadIdx.x;
    const int g = t >> 6;          // 0=r, 1=z, 2=n
    const int j = t & 63;
    const int seq0 = blockIdx.x * SPB;

    // cache this thread's Whh row (packed pairs along k) + Wih row + biases
    unsigned long long w2[NH / 2];
#pragma unroll
    for (int k = 0; k < NH / 2; k++)
        w2[k] = pack2(Whh[t * NH + 2*k], Whh[t * NH + 2*k + 1]);
    const float wi0 = Wih[t*4 + 0], wi1 = Wih[t*4 + 1];
    const float wi2 = Wih[t*4 + 2], wi3 = Wih[t*4 + 3];
    const float b_i = bih[t], b_h = bhh[t];

    // stage all x for this block's sequences (contiguous: g_x[seq0*256 ...])
    for (int idx = t; idx < SPB * NT * 4; idx += GRU_THREADS)
        sh_x[idx >> 8][idx & 255] = g_x[seq0 * (NT*4) + idx];
    for (int idx = t; idx < SPB * NH; idx += GRU_THREADS)
        sh_h[idx >> 6][idx & 63] = 0.0f;
    __syncthreads();

    for (int step = 0; step < NT; step++) {
        // ---- phase 1: gate pre-activations (packed matvec vs h) ----
        unsigned long long acc2[SPB];
#pragma unroll
        for (int s = 0; s < SPB; s++) acc2[s] = 0ull;   // bits of {0f,0f}

#pragma unroll
        for (int k4 = 0; k4 < NH / 4; k4++) {
#pragma unroll
            for (int s = 0; s < SPB; s++) {
                // 16B broadcast load: two packed {h[k],h[k+1]} pairs
                ulonglong2 h2 = *reinterpret_cast<const ulonglong2*>(&sh_h[s][k4 * 4]);
                fma2(acc2[s], w2[2*k4 + 0], h2.x);
                fma2(acc2[s], w2[2*k4 + 1], h2.y);
            }
        }

#pragma unroll
        for (int s = 0; s < SPB; s++) {
            const float* xs = &sh_x[s][step * 4];
            float gi = b_i + wi0 * xs[0] + wi1 * xs[1] + wi2 * xs[2] + wi3 * xs[3];
            float2 a = unpack2(acc2[s]);
            float gh = b_h + (a.x + a.y);
            if (g < 2) {
                sh_pre[g][s][j] = gi + gh;
            } else {
                sh_pre[2][s][j] = gi;
                sh_pre[3][s][j] = gh;
            }
        }
        __syncthreads();

        // ---- phase 2: gate nonlinearity + hidden update ----
        for (int idx = t; idx < SPB * NH; idx += GRU_THREADS) {
            int s = idx >> 6, jj = idx & 63;
            float r    = sigf(sh_pre[0][s][jj]);
            float z    = sigf(sh_pre[1][s][jj]);
            float cand = tanhf(fmaf(r, sh_pre[3][s][jj], sh_pre[2][s][jj]));
            float hp   = sh_h[s][jj];
            sh_h[s][jj] = fmaf(z, hp - cand, cand);   // (1-z)*cand + z*hp
        }
        __syncthreads();
    }

    for (int idx = t; idx < SPB * NH; idx += GRU_THREADS)
        g_hidden[seq0 * NH + idx] = sh_h[idx >> 6][idx & 63];
}

// ---------------------------------------------------------------------------
// Kernel 3: lane MLP + phase competition head. One block per batch element.
// ---------------------------------------------------------------------------
__constant__ int c_PL[8][2] = {{1,3},{0,2},{5,7},{4,6},{0,1},{2,3},{4,5},{6,7}};

__global__ __launch_bounds__(64)
void post_kernel(const float* __restrict__ feat,
                 const int*   __restrict__ relation,
                 const float* __restrict__ emb_phase,
                 const float* __restrict__ Wv,  const float* __restrict__ bv,
                 const float* __restrict__ Wl,  const float* __restrict__ bl,
                 const float* __restrict__ emb_const,
                 const float* __restrict__ Wcf, const float* __restrict__ bcf,
                 const float* __restrict__ Wcc, const float* __restrict__ bcc,
                 const float* __restrict__ Wcm, const float* __restrict__ bcm,
                 const float* __restrict__ Wfin,const float* __restrict__ bfin,
                 float* __restrict__ out)
{
    __shared__ float s_hid[NL][NH];        // 2 KB
    __shared__ float s_lf[NL][8];          // veh(4) + ph(4)
    __shared__ float s_line[NL][16];
    __shared__ float s_pp[NL][16];
    __shared__ float s_Wl[16 * 72];        // 4.5 KB
    __shared__ float s_yc[NL][7][20];      // 4.4 KB
    __shared__ float s_val[NL][7];

    const int tid = threadIdx.x;
    const int b = blockIdx.x;

    for (int i = tid; i < NL * NH; i += 64)
        s_hid[i >> 6][i & 63] = g_hidden[b * (NL * NH) + i];
    for (int i = tid; i < 16 * 72; i += 64)
        s_Wl[i] = Wl[i];

    // veh + ph (64 values)
    {
        int l = tid >> 3, c4 = tid & 7;
        if (c4 < 4) {
            float vr = feat[b * 16 + 8 + l];
            s_lf[l][c4] = sigf(fmaf(vr, Wv[c4], bv[c4]));
        } else {
            int c = c4 - 4;
            int pid = (int)feat[b * 16 + l];
            s_lf[l][c4] = sigf(emb_phase[pid * 4 + c]);
        }
    }

    // yc (constant per (p,q)): relu(emb_const[relation] @ Wcc^T + bcc)
    for (int i = tid; i < NL * 7 * 20; i += 64) {
        int o = i % 20, pq = i / 20;
        int p = pq / 7, q = pq % 7;
        const float* ce = emb_const + relation[p * 7 + q] * 4;
        float v = bcc[o];
#pragma unroll
        for (int c = 0; c < 4; c++) v = fmaf(ce[c], Wcc[o * 4 + c], v);
        s_yc[p][q][o] = fmaxf(v, 0.0f);
    }
    __syncthreads();

    // line = relu(lane_feat @ Wl^T + bl)  (128 outputs)
    for (int i = tid; i < NL * 16; i += 64) {
        int l = i >> 4, o = i & 15;
        const float* wrow = &s_Wl[o * 72];
        float v = bl[o];
#pragma unroll
        for (int c = 0; c < 8; c++)  v = fmaf(s_lf[l][c], wrow[c], v);
#pragma unroll
        for (int k = 0; k < NH; k++) v = fmaf(s_hid[l][k], wrow[8 + k], v);
        s_line[l][o] = fmaxf(v, 0.0f);
    }
    __syncthreads();

    // pp[p] = line[PL[p][0]] + line[PL[p][1]]
    for (int i = tid; i < NL * 16; i += 64) {
        int p = i >> 4, o = i & 15;
        s_pp[p][o] = s_line[c_PL[p][0]][o] + s_line[c_PL[p][1]][o];
    }
    __syncthreads();

    // per-(p,q) competition MLP (56 pairs -> threads 0..55)
    if (tid < 56) {
        int p = tid / 7, qi = tid % 7;
        int jq = (qi < p) ? qi : qi + 1;

        float xf[20];
#pragma unroll
        for (int o = 0; o < 20; o++) {
            const float* wc = Wcf + o * 32;
            float v = bcf[o];
#pragma unroll
            for (int c = 0; c < 16; c++) v = fmaf(s_pp[p][c],  wc[c],      v);
#pragma unroll
            for (int c = 0; c < 16; c++) v = fmaf(s_pp[jq][c], wc[16 + c], v);
            xf[o] = fmaxf(v, 0.0f) * s_yc[p][qi][o];
        }
        float val = bfin[0];
#pragma unroll
        for (int o = 0; o < 20; o++) {
            const float* wm = Wcm + o * 20;
            float v = bcm[o];
#pragma unroll
            for (int c = 0; c < 20; c++) v = fmaf(xf[c], wm[c], v);
            val = fmaf(fmaxf(v, 0.0f), Wfin[o], val);
        }
        s_val[p][qi] = val;
    }
    __syncthreads();

    if (tid < NL) {
        float acc = 0.0f;
#pragma unroll
        for (int q = 0; q < 7; q++) acc += s_val[tid][q];
        out[b * NL + tid] = acc;
    }
}

// ---------------------------------------------------------------------------
// Launch
// ---------------------------------------------------------------------------
extern "C" void kernel_launch(void* const* d_in, const int* in_sizes, int n_in,
                              void* d_out, int out_size)
{
    const float* feature  = (const float*)d_in[0];
    const float* history  = (const float*)d_in[1];
    const int*   relation = (const int*)  d_in[2];
    const float* emb_phase= (const float*)d_in[3];
    const float* Wv       = (const float*)d_in[4];
    const float* bv       = (const float*)d_in[5];
    const float* Wh       = (const float*)d_in[6];
    const float* bh       = (const float*)d_in[7];
    const float* Wih      = (const float*)d_in[8];
    const float* Whh      = (const float*)d_in[9];
    const float* bih      = (const float*)d_in[10];
    const float* bhh      = (const float*)d_in[11];
    const float* Wl       = (const float*)d_in[12];
    const float* bl       = (const float*)d_in[13];
    const float* emb_const= (const float*)d_in[14];
    const float* Wcf      = (const float*)d_in[15];
    const float* bcf      = (const float*)d_in[16];
    const float* Wcc      = (const float*)d_in[17];
    const float* bcc      = (const float*)d_in[18];
    const float* Wcm      = (const float*)d_in[19];
    const float* bcm      = (const float*)d_in[20];
    const float* Wfin     = (const float*)d_in[21];
    const float* bfin     = (const float*)d_in[22];
    float* out = (float*)d_out;

    {
        int total = NB * NT * NL;
        int threads = 256;
        prep_kernel<<<(total + threads - 1) / threads, threads>>>(history, Wh, bh);
    }
    gru_kernel<<<NSEQ / SPB, GRU_THREADS>>>(Wih, Whh, bih, bhh);
    post_kernel<<<NB, 64>>>(feature, relation, emb_phase, Wv, bv, Wl, bl,
                            emb_const, Wcf, bcf, Wcc, bcc, Wcm, bcm,
                            Wfin, bfin, out);
}

// round 4
// speedup vs baseline: 3.2051x; 3.1686x over previous
#include <cuda_runtime.h>
#include <cuda_bf16.h>
#include <stdint.h>
#include <math.h>

#define NB   2048
#define NT   64
#define NL   8
#define NH   64
#define NSEQ (NB*NL)          // 16384
#define RPC  64               // rows per GRU CTA
#define GCTA (NSEQ/RPC)       // 256 CTAs
#define GT   256              // GRU threads per CTA

// ---- SMEM map (bytes) -----------------------------------------------------
#define SO_B    0                  // B frags: 2 splits x 24 ntiles x 4 kt x 256B = 48 KB
#define SO_A    49152              // A frags: 2 buf x 2 splits x 4 mtg x 4 kt x 512B = 32 KB
#define SO_X    (49152 + 32768)    // x stage: 2 buf x 64 rows x 16B = 2 KB
#define SO_WT   (SO_X + 2048)      // Wtab: 64 j x 16 floats = 4 KB
#define SMEMSZ  (SO_WT + 4096)     // 88064 B -> 2 CTAs/SM

// ---- scratch (__device__ globals; allocs forbidden) -----------------------
__device__ float    g_x[NT * NSEQ * 4];        // [t][seq][4]
__device__ float    g_hidden[NSEQ * NH];       // [seq][64]
__device__ uint32_t g_B[2 * 24 * 4 * 32 * 2];  // fragment-linear Whh hi/lo

__device__ __forceinline__ float sigf(float x) {
    return __fdividef(1.0f, 1.0f + __expf(-x));
}
__device__ __forceinline__ float tanhfast(float x) {
    return __fdividef(2.0f, 1.0f + __expf(-2.0f * x)) - 1.0f;
}

// mma.sync m16n8k16 bf16 -> f32 accumulate (sm_80+ PTX; no 'a' features)
__device__ __forceinline__ void hmma(float c[4],
                                     uint32_t a0, uint32_t a1, uint32_t a2, uint32_t a3,
                                     uint32_t b0, uint32_t b1) {
    asm("mma.sync.aligned.m16n8k16.row.col.f32.bf16.bf16.f32 "
        "{%0,%1,%2,%3},{%4,%5,%6,%7},{%8,%9},{%0,%1,%2,%3};"
        : "+f"(c[0]), "+f"(c[1]), "+f"(c[2]), "+f"(c[3])
        : "r"(a0), "r"(a1), "r"(a2), "r"(a3), "r"(b0), "r"(b1));
}

// ---------------------------------------------------------------------------
// Kernel 0: pack Whh (hi/lo bf16) into fragment-linear layout.
// Index: (((s*24 + ntile)*4 + kt)*32 + lane) * 2 u32.
// B frag (col-major 16x8): reg0 = {W[n][k0], W[n][k0+1]}, reg1 = {k0+8, k0+9},
// n = ntile*8 + lane/4, k0 = kt*16 + 2*(lane%4).
// ---------------------------------------------------------------------------
__global__ void build_B(const float* __restrict__ Whh)
{
    int i = blockIdx.x * blockDim.x + threadIdx.x;
    if (i >= 2 * 24 * 4 * 32) return;
    int lane = i & 31;
    int kt = (i >> 5) & 3;
    int ntile = (i >> 7) % 24;
    int s = i / (24 * 4 * 32);
    int n = ntile * 8 + (lane >> 2);
    int k0 = kt * 16 + 2 * (lane & 3);

    float w[4] = { Whh[n * 64 + k0],     Whh[n * 64 + k0 + 1],
                   Whh[n * 64 + k0 + 8], Whh[n * 64 + k0 + 9] };
    __nv_bfloat16 v[4];
#pragma unroll
    for (int q = 0; q < 4; q++) {
        __nv_bfloat16 hi = __float2bfloat16(w[q]);
        v[q] = (s == 0) ? hi : __float2bfloat16(w[q] - __bfloat162float(hi));
    }
    __nv_bfloat162 r0(v[0], v[1]), r1(v[2], v[3]);
    g_B[i * 2 + 0] = *reinterpret_cast<uint32_t*>(&r0);
    g_B[i * 2 + 1] = *reinterpret_cast<uint32_t*>(&r1);
}

// ---------------------------------------------------------------------------
// Kernel 1: history gather + (3->4) matmul + sigmoid => g_x [t][seq][4]
// ---------------------------------------------------------------------------
__global__ void prep_kernel(const float* __restrict__ hist,
                            const float* __restrict__ Wh,
                            const float* __restrict__ bh)
{
    int idx = blockIdx.x * blockDim.x + threadIdx.x;
    if (idx >= NB * NT * NL) return;
    int l = idx & 7;
    int t = (idx >> 3) & 63;
    int b = idx >> 9;

    const float* hp = hist + (b * NT + t) * 24;
    float h0 = hp[l], h1 = hp[l + 8], h2 = hp[l + 16];

    float* xp = g_x + ((size_t)t * NSEQ + (b * NL + l)) * 4;
#pragma unroll
    for (int o = 0; o < 4; o++) {
        float v = bh[o] + Wh[o*3 + 0]*h0 + Wh[o*3 + 1]*h1 + Wh[o*3 + 2]*h2;
        xp[o] = sigf(v);
    }
}

// ---------------------------------------------------------------------------
// Kernel 2: tensor-core GRU via mma.sync (bf16, 3-product hi/lo split).
// CTA = 64 rows, 256 threads = 8 warps (mg in {0,1} = 32-row group,
// ng in {0..3} = 16-j block). Per step per warp: 144 HMMA.
// ---------------------------------------------------------------------------
__device__ __forceinline__ float gru_one(float ar, float az, float an,
                                         float4 x, float4 wr, float4 wz, float4 wn,
                                         float br, float bz, float bin, float bhn,
                                         float hp)
{
    float gir = br  + x.x*wr.x + x.y*wr.y + x.z*wr.z + x.w*wr.w;
    float giz = bz  + x.x*wz.x + x.y*wz.y + x.z*wz.z + x.w*wz.w;
    float gin = bin + x.x*wn.x + x.y*wn.y + x.z*wn.z + x.w*wn.w;
    float r = sigf(ar + gir);
    float z = sigf(az + giz);
    float cand = tanhfast(fmaf(r, an + bhn, gin));
    return fmaf(z, hp - cand, cand);
}

__global__ void __launch_bounds__(GT, 2)
gru_kernel(const float* __restrict__ Wih,
           const float* __restrict__ bih,
           const float* __restrict__ bhh)
{
    extern __shared__ char smem[];
    const int tid = threadIdx.x;
    const int l   = tid & 31;
    const int wid = tid >> 5;
    const int mg  = wid >> 2;       // 0,1 : 32-row group
    const int ng  = wid & 3;        // 0..3: 16-j block
    const int c4  = l & 3;
    const int lr  = l >> 2;
    const int seq0 = blockIdx.x * RPC;

    // ---- stage B (48 KB), zero A buf0 (16 KB), build Wtab, stage x(t=0) ----
    {
        const uint4* src = (const uint4*)g_B;
        uint4* dst = (uint4*)(smem + SO_B);
#pragma unroll
        for (int i = 0; i < 12; i++) dst[tid + i * GT] = src[tid + i * GT];
        uint4 z; z.x = z.y = z.z = z.w = 0u;
        uint4* da = (uint4*)(smem + SO_A);
#pragma unroll
        for (int i = 0; i < 4; i++) da[tid + i * GT] = z;
    }
    for (int idx = tid; idx < 1024; idx += GT) {
        int j = idx >> 4, f = idx & 15;
        float v;
        if      (f < 4)   v = Wih[j * 4 + f];
        else if (f < 8)   v = Wih[(64 + j) * 4 + (f - 4)];
        else if (f < 12)  v = Wih[(128 + j) * 4 + (f - 8)];
        else if (f == 12) v = bih[j] + bhh[j];
        else if (f == 13) v = bih[64 + j] + bhh[64 + j];
        else if (f == 14) v = bih[128 + j];
        else              v = bhh[128 + j];
        *(float*)(smem + SO_WT + idx * 4) = v;
    }
    if (tid < 64)
        *(float4*)(smem + SO_X + tid * 16) = *(const float4*)(g_x + (size_t)(seq0 + tid) * 4);
    __syncthreads();

    float hprev[2][2][2][2];   // [mt][rh][sub][jp]
#pragma unroll
    for (int a = 0; a < 2; a++)
#pragma unroll
        for (int b = 0; b < 2; b++)
#pragma unroll
            for (int c = 0; c < 2; c++) { hprev[a][b][c][0] = 0.f; hprev[a][b][c][1] = 0.f; }

#pragma unroll 1
    for (int t = 0; t < NT; t++) {
        const int buf = t & 1, bufn = buf ^ 1;

        float4 xn;
        if (tid < 64 && t + 1 < NT)
            xn = *(const float4*)(g_x + ((size_t)(t + 1) * NSEQ + seq0 + tid) * 4);

        float acc[2][3][2][4];
#pragma unroll
        for (int mt = 0; mt < 2; mt++)
#pragma unroll
            for (int gt = 0; gt < 3; gt++)
#pragma unroll
                for (int sb = 0; sb < 2; sb++)
#pragma unroll
                    for (int r = 0; r < 4; r++) acc[mt][gt][sb][r] = 0.0f;

        // ---- HMMA mainloop: K streamed, B hi/lo per n-tile -----------------
#pragma unroll
        for (int kt = 0; kt < 4; kt++) {
            uint4 ah[2], al[2];
#pragma unroll
            for (int mt = 0; mt < 2; mt++) {
                int mtg = mg * 2 + mt;
                ah[mt] = *(const uint4*)(smem + SO_A + (size_t)(((buf*2 + 0)*4 + mtg)*4 + kt)*512 + l*16);
                al[mt] = *(const uint4*)(smem + SO_A + (size_t)(((buf*2 + 1)*4 + mtg)*4 + kt)*512 + l*16);
            }
#pragma unroll
            for (int gt = 0; gt < 3; gt++)
#pragma unroll
            for (int sb = 0; sb < 2; sb++) {
                int ntile = gt * 8 + ng * 2 + sb;
                uint2 bhi = *(const uint2*)(smem + SO_B + (size_t)(((0*24 + ntile)*4 + kt))*256 + l*8);
                hmma(acc[0][gt][sb], ah[0].x, ah[0].y, ah[0].z, ah[0].w, bhi.x, bhi.y);
                hmma(acc[1][gt][sb], ah[1].x, ah[1].y, ah[1].z, ah[1].w, bhi.x, bhi.y);
                hmma(acc[0][gt][sb], al[0].x, al[0].y, al[0].z, al[0].w, bhi.x, bhi.y);
                hmma(acc[1][gt][sb], al[1].x, al[1].y, al[1].z, al[1].w, bhi.x, bhi.y);
                uint2 blo = *(const uint2*)(smem + SO_B + (size_t)(((1*24 + ntile)*4 + kt))*256 + l*8);
                hmma(acc[0][gt][sb], ah[0].x, ah[0].y, ah[0].z, ah[0].w, blo.x, blo.y);
                hmma(acc[1][gt][sb], ah[1].x, ah[1].y, ah[1].z, ah[1].w, blo.x, blo.y);
            }
        }

        // ---- epilogue: gates + h update + write bf16 hi/lo A frags ---------
#pragma unroll
        for (int sb = 0; sb < 2; sb++) {
            const int j0 = ng * 16 + sb * 8 + 2 * c4;
            const float4* wt0 = (const float4*)(smem + SO_WT + (size_t)j0 * 64);
            const float4* wt1 = (const float4*)(smem + SO_WT + (size_t)(j0 + 1) * 64);
            float4 wr0 = wt0[0], wz0 = wt0[1], wn0 = wt0[2], bb0 = wt0[3];
            float4 wr1 = wt1[0], wz1 = wt1[1], wn1 = wt1[2], bb1 = wt1[3];
#pragma unroll
            for (int mt = 0; mt < 2; mt++)
#pragma unroll
            for (int rh = 0; rh < 2; rh++) {
                const int m = mg * 32 + mt * 16 + rh * 8 + lr;
                float4 xv = *(const float4*)(smem + SO_X + buf * 1024 + m * 16);
                const int rg = rh * 2;
                float h0 = gru_one(acc[mt][0][sb][rg],   acc[mt][1][sb][rg],   acc[mt][2][sb][rg],
                                   xv, wr0, wz0, wn0, bb0.x, bb0.y, bb0.z, bb0.w,
                                   hprev[mt][rh][sb][0]);
                float h1 = gru_one(acc[mt][0][sb][rg+1], acc[mt][1][sb][rg+1], acc[mt][2][sb][rg+1],
                                   xv, wr1, wz1, wn1, bb1.x, bb1.y, bb1.z, bb1.w,
                                   hprev[mt][rh][sb][1]);
                hprev[mt][rh][sb][0] = h0;
                hprev[mt][rh][sb][1] = h1;

                float2 hv; hv.x = h0; hv.y = h1;
                __nv_bfloat162 hi2 = __float22bfloat162_rn(hv);
                float f0 = __bfloat162float(hi2.x), f1 = __bfloat162float(hi2.y);
                float2 lv; lv.x = h0 - f0; lv.y = h1 - f1;
                __nv_bfloat162 lo2 = __float22bfloat162_rn(lv);

                const int mtg = mg * 2 + mt;
                const size_t roff = (size_t)l * 16 + (rh + 2 * sb) * 4;
                *(uint32_t*)(smem + SO_A + (size_t)(((bufn*2 + 0)*4 + mtg)*4 + ng)*512 + roff)
                    = *reinterpret_cast<uint32_t*>(&hi2);
                *(uint32_t*)(smem + SO_A + (size_t)(((bufn*2 + 1)*4 + mtg)*4 + ng)*512 + roff)
                    = *reinterpret_cast<uint32_t*>(&lo2);

                if (t == NT - 1)
                    *(float2*)(&g_hidden[(size_t)(seq0 + m) * NH + j0]) = hv;
            }
        }
        if (tid < 64 && t + 1 < NT)
            *(float4*)(smem + SO_X + bufn * 1024 + tid * 16) = xn;
        __syncthreads();
    }
}

// ---------------------------------------------------------------------------
// Kernel 3: lane MLP + phase competition head. One block per batch element.
// ---------------------------------------------------------------------------
__constant__ int c_PL[8][2] = {{1,3},{0,2},{5,7},{4,6},{0,1},{2,3},{4,5},{6,7}};

__global__ void __launch_bounds__(64)
post_kernel(const float* __restrict__ feat,
            const int*   __restrict__ relation,
            const float* __restrict__ emb_phase,
            const float* __restrict__ Wv,  const float* __restrict__ bv,
            const float* __restrict__ Wl,  const float* __restrict__ bl,
            const float* __restrict__ emb_const,
            const float* __restrict__ Wcf, const float* __restrict__ bcf,
            const float* __restrict__ Wcc, const float* __restrict__ bcc,
            const float* __restrict__ Wcm, const float* __restrict__ bcm,
            const float* __restrict__ Wfin,const float* __restrict__ bfin,
            float* __restrict__ out)
{
    __shared__ float s_hid[NL][NH];
    __shared__ float s_lf[NL][8];
    __shared__ float s_line[NL][16];
    __shared__ float s_pp[NL][16];
    __shared__ float s_Wl[16 * 72];
    __shared__ float s_yc[NL][7][20];
    __shared__ float s_val[NL][7];

    const int tid = threadIdx.x;
    const int b = blockIdx.x;

    for (int i = tid; i < NL * NH; i += 64)
        s_hid[i >> 6][i & 63] = g_hidden[(size_t)b * (NL * NH) + i];
    for (int i = tid; i < 16 * 72; i += 64)
        s_Wl[i] = Wl[i];

    {
        int l = tid >> 3, f = tid & 7;
        if (f < 4) {
            float vr = feat[b * 16 + 8 + l];
            s_lf[l][f] = sigf(fmaf(vr, Wv[f], bv[f]));
        } else {
            int c = f - 4;
            int pid = (int)feat[b * 16 + l];
            s_lf[l][f] = sigf(emb_phase[pid * 4 + c]);
        }
    }

    for (int i = tid; i < NL * 7 * 20; i += 64) {
        int o = i % 20, pq = i / 20;
        int p = pq / 7, q = pq % 7;
        const float* ce = emb_const + relation[p * 7 + q] * 4;
        float v = bcc[o];
#pragma unroll
        for (int c = 0; c < 4; c++) v = fmaf(ce[c], Wcc[o * 4 + c], v);
        s_yc[p][q][o] = fmaxf(v, 0.0f);
    }
    __syncthreads();

    for (int i = tid; i < NL * 16; i += 64) {
        int l = i >> 4, o = i & 15;
        const float* wrow = &s_Wl[o * 72];
        float v = bl[o];
#pragma unroll
        for (int c = 0; c < 8; c++)  v = fmaf(s_lf[l][c], wrow[c], v);
#pragma unroll
        for (int k = 0; k < NH; k++) v = fmaf(s_hid[l][k], wrow[8 + k], v);
        s_line[l][o] = fmaxf(v, 0.0f);
    }
    __syncthreads();

    for (int i = tid; i < NL * 16; i += 64) {
        int p = i >> 4, o = i & 15;
        s_pp[p][o] = s_line[c_PL[p][0]][o] + s_line[c_PL[p][1]][o];
    }
    __syncthreads();

    if (tid < 56) {
        int p = tid / 7, qi = tid % 7;
        int jq = (qi < p) ? qi : qi + 1;

        float xf[20];
#pragma unroll
        for (int o = 0; o < 20; o++) {
            const float* wc = Wcf + o * 32;
            float v = bcf[o];
#pragma unroll
            for (int c = 0; c < 16; c++) v = fmaf(s_pp[p][c],  wc[c],      v);
#pragma unroll
            for (int c = 0; c < 16; c++) v = fmaf(s_pp[jq][c], wc[16 + c], v);
            xf[o] = fmaxf(v, 0.0f) * s_yc[p][qi][o];
        }
        float val = bfin[0];
#pragma unroll
        for (int o = 0; o < 20; o++) {
            const float* wm = Wcm + o * 20;
            float v = bcm[o];
#pragma unroll
            for (int c = 0; c < 20; c++) v = fmaf(xf[c], wm[c], v);
            val = fmaf(fmaxf(v, 0.0f), Wfin[o], val);
        }
        s_val[p][qi] = val;
    }
    __syncthreads();

    if (tid < NL) {
        float acc = 0.0f;
#pragma unroll
        for (int q = 0; q < 7; q++) acc += s_val[tid][q];
        out[b * NL + tid] = acc;
    }
}

// ---------------------------------------------------------------------------
// Launch
// ---------------------------------------------------------------------------
extern "C" void kernel_launch(void* const* d_in, const int* in_sizes, int n_in,
                              void* d_out, int out_size)
{
    const float* feature  = (const float*)d_in[0];
    const float* history  = (const float*)d_in[1];
    const int*   relation = (const int*)  d_in[2];
    const float* emb_phase= (const float*)d_in[3];
    const float* Wv       = (const float*)d_in[4];
    const float* bv       = (const float*)d_in[5];
    const float* Wh       = (const float*)d_in[6];
    const float* bh       = (const float*)d_in[7];
    const float* Wih      = (const float*)d_in[8];
    const float* Whh      = (const float*)d_in[9];
    const float* bih      = (const float*)d_in[10];
    const float* bhh      = (const float*)d_in[11];
    const float* Wl       = (const float*)d_in[12];
    const float* bl       = (const float*)d_in[13];
    const float* emb_const= (const float*)d_in[14];
    const float* Wcf      = (const float*)d_in[15];
    const float* bcf      = (const float*)d_in[16];
    const float* Wcc      = (const float*)d_in[17];
    const float* bcc      = (const float*)d_in[18];
    const float* Wcm      = (const float*)d_in[19];
    const float* bcm      = (const float*)d_in[20];
    const float* Wfin     = (const float*)d_in[21];
    const float* bfin     = (const float*)d_in[22];
    float* out = (float*)d_out;

    cudaFuncSetAttribute(gru_kernel, cudaFuncAttributeMaxDynamicSharedMemorySize, SMEMSZ);

    build_B<<<(2*24*4*32 + 255) / 256, 256>>>(Whh);
    {
        int total = NB * NT * NL;
        prep_kernel<<<(total + 255) / 256, 256>>>(history, Wh, bh);
    }
    gru_kernel<<<GCTA, GT, SMEMSZ>>>(Wih, bih, bhh);
    post_kernel<<<NB, 64>>>(feature, relation, emb_phase, Wv, bv, Wl, bl,
                            emb_const, Wcf, bcf, Wcc, bcc, Wcm, bcm,
                            Wfin, bfin, out);
}

// round 5
// speedup vs baseline: 3.4914x; 1.0893x over previous
#include <cuda_runtime.h>
#include <cuda_bf16.h>
#include <stdint.h>
#include <math.h>

#define NB   2048
#define NT   64
#define NL   8
#define NH   64
#define NSEQ (NB*NL)          // 16384
#define RPC  64               // rows per GRU CTA
#define GCTA (NSEQ/RPC)       // 256 CTAs
#define GT   256              // GRU threads per CTA

// ---- SMEM map (bytes) -----------------------------------------------------
#define SO_B    0                  // B frags: 2 splits x 24 ntiles x 4 kt x 256B = 48 KB
#define SO_A    49152              // A frags: 2 buf x 2 splits x 4 mtg x 4 kt x 512B = 32 KB
#define SO_X    (49152 + 32768)    // x stage: 2 buf x 64 rows x 16B = 2 KB
#define SO_WT   (SO_X + 2048)      // Wtab: 64 j x 16 floats = 4 KB
#define SMEMSZ  (SO_WT + 4096)     // 88064 B -> 2 CTAs/SM

// ---- scratch (__device__ globals; allocs forbidden) -----------------------
__device__ float    g_x[NT * NSEQ * 4];        // [t][seq][4]
__device__ float    g_hidden[NSEQ * NH];       // [seq][64]
__device__ uint32_t g_B[2 * 24 * 4 * 32 * 2];  // fragment-linear Whh hi/lo
__device__ float    g_yc[NL * 7 * 20];         // batch-invariant relu(ce@Wcc^T+bcc)

__device__ __forceinline__ float sigf(float x) {
    return __fdividef(1.0f, 1.0f + __expf(-x));
}
__device__ __forceinline__ float tanha(float x) {
    float y;
    asm("tanh.approx.f32 %0, %1;" : "=f"(y) : "f"(x));
    return y;
}
__device__ __forceinline__ float siga(float x) {     // sigmoid via tanh, 1 MUFU
    return fmaf(0.5f, tanha(0.5f * x), 0.5f);
}

// mma.sync m16n8k16 bf16 -> f32 accumulate (sm_80+ PTX; no 'a' features)
__device__ __forceinline__ void hmma(float c[4],
                                     uint32_t a0, uint32_t a1, uint32_t a2, uint32_t a3,
                                     uint32_t b0, uint32_t b1) {
    asm("mma.sync.aligned.m16n8k16.row.col.f32.bf16.bf16.f32 "
        "{%0,%1,%2,%3},{%4,%5,%6,%7},{%8,%9},{%0,%1,%2,%3};"
        : "+f"(c[0]), "+f"(c[1]), "+f"(c[2]), "+f"(c[3])
        : "r"(a0), "r"(a1), "r"(a2), "r"(a3), "r"(b0), "r"(b1));
}

// ---------------------------------------------------------------------------
// Kernel 0: pack Whh (hi/lo bf16) into fragment-linear layout.
// ---------------------------------------------------------------------------
__global__ void build_B(const float* __restrict__ Whh)
{
    int i = blockIdx.x * blockDim.x + threadIdx.x;
    if (i >= 2 * 24 * 4 * 32) return;
    int lane = i & 31;
    int kt = (i >> 5) & 3;
    int ntile = (i >> 7) % 24;
    int s = i / (24 * 4 * 32);
    int n = ntile * 8 + (lane >> 2);
    int k0 = kt * 16 + 2 * (lane & 3);

    float w[4] = { Whh[n * 64 + k0],     Whh[n * 64 + k0 + 1],
                   Whh[n * 64 + k0 + 8], Whh[n * 64 + k0 + 9] };
    __nv_bfloat16 v[4];
#pragma unroll
    for (int q = 0; q < 4; q++) {
        __nv_bfloat16 hi = __float2bfloat16(w[q]);
        v[q] = (s == 0) ? hi : __float2bfloat16(w[q] - __bfloat162float(hi));
    }
    __nv_bfloat162 r0(v[0], v[1]), r1(v[2], v[3]);
    g_B[i * 2 + 0] = *reinterpret_cast<uint32_t*>(&r0);
    g_B[i * 2 + 1] = *reinterpret_cast<uint32_t*>(&r1);
}

// Kernel 0b: batch-invariant yc table
__global__ void build_yc(const int* __restrict__ relation,
                         const float* __restrict__ emb_const,
                         const float* __restrict__ Wcc,
                         const float* __restrict__ bcc)
{
    int i = blockIdx.x * blockDim.x + threadIdx.x;
    if (i >= NL * 7 * 20) return;
    int o = i % 20, pq = i / 20;
    int p = pq / 7, q = pq % 7;
    const float* ce = emb_const + relation[p * 7 + q] * 4;
    float v = bcc[o];
#pragma unroll
    for (int c = 0; c < 4; c++) v = fmaf(ce[c], Wcc[o * 4 + c], v);
    g_yc[i] = fmaxf(v, 0.0f);
}

// ---------------------------------------------------------------------------
// Kernel 1: history gather + (3->4) matmul + sigmoid => g_x [t][seq][4]
// ---------------------------------------------------------------------------
__global__ void prep_kernel(const float* __restrict__ hist,
                            const float* __restrict__ Wh,
                            const float* __restrict__ bh)
{
    int idx = blockIdx.x * blockDim.x + threadIdx.x;
    if (idx >= NB * NT * NL) return;
    int l = idx & 7;
    int t = (idx >> 3) & 63;
    int b = idx >> 9;

    const float* hp = hist + (b * NT + t) * 24;
    float h0 = hp[l], h1 = hp[l + 8], h2 = hp[l + 16];

    float* xp = g_x + ((size_t)t * NSEQ + (b * NL + l)) * 4;
#pragma unroll
    for (int o = 0; o < 4; o++) {
        float v = bh[o] + Wh[o*3 + 0]*h0 + Wh[o*3 + 1]*h1 + Wh[o*3 + 2]*h2;
        xp[o] = sigf(v);
    }
}

// ---------------------------------------------------------------------------
// Kernel 2: tensor-core GRU via mma.sync (bf16, 3-product hi/lo split).
// CTA = 64 rows, 256 threads = 8 warps. Warp (mg,ng) produces exactly the
// A-tiles consumed by its own mg-group -> per-group named barriers.
// ---------------------------------------------------------------------------
__device__ __forceinline__ float gru_one(float ar, float az, float an,
                                         float4 x, float4 wr, float4 wz, float4 wn,
                                         float br, float bz, float bin, float bhn,
                                         float hp)
{
    float gir = br  + x.x*wr.x + x.y*wr.y + x.z*wr.z + x.w*wr.w;
    float giz = bz  + x.x*wz.x + x.y*wz.y + x.z*wz.z + x.w*wz.w;
    float gin = bin + x.x*wn.x + x.y*wn.y + x.z*wn.z + x.w*wn.w;
    float r = siga(ar + gir);
    float z = siga(az + giz);
    float cand = tanha(fmaf(r, an + bhn, gin));
    return fmaf(z, hp - cand, cand);
}

__global__ void __launch_bounds__(GT, 2)
gru_kernel(const float* __restrict__ Wih,
           const float* __restrict__ bih,
           const float* __restrict__ bhh)
{
    extern __shared__ char smem[];
    const int tid = threadIdx.x;
    const int l   = tid & 31;
    const int wid = tid >> 5;
    const int mg  = wid >> 2;       // 0,1 : 32-row group
    const int ng  = wid & 3;        // 0..3: 16-j block == kt produced
    const int gtid = tid & 127;     // thread index within mg group
    const int c4  = l & 3;
    const int lr  = l >> 2;
    const int seq0 = blockIdx.x * RPC;

    // ---- stage B (48 KB), zero A buf0 (16 KB), build Wtab, stage x(t=0) ----
    {
        const uint4* src = (const uint4*)g_B;
        uint4* dst = (uint4*)(smem + SO_B);
#pragma unroll
        for (int i = 0; i < 12; i++) dst[tid + i * GT] = src[tid + i * GT];
        uint4 z; z.x = z.y = z.z = z.w = 0u;
        uint4* da = (uint4*)(smem + SO_A);
#pragma unroll
        for (int i = 0; i < 4; i++) da[tid + i * GT] = z;
    }
    for (int idx = tid; idx < 1024; idx += GT) {
        int j = idx >> 4, f = idx & 15;
        float v;
        if      (f < 4)   v = Wih[j * 4 + f];
        else if (f < 8)   v = Wih[(64 + j) * 4 + (f - 4)];
        else if (f < 12)  v = Wih[(128 + j) * 4 + (f - 8)];
        else if (f == 12) v = bih[j] + bhh[j];
        else if (f == 13) v = bih[64 + j] + bhh[64 + j];
        else if (f == 14) v = bih[128 + j];
        else              v = bhh[128 + j];
        *(float*)(smem + SO_WT + idx * 4) = v;
    }
    if (tid < 64)
        *(float4*)(smem + SO_X + tid * 16) = *(const float4*)(g_x + (size_t)(seq0 + tid) * 4);
    __syncthreads();

    float hprev[2][2][2][2];   // [mt][rh][sub][jp]
#pragma unroll
    for (int a = 0; a < 2; a++)
#pragma unroll
        for (int b = 0; b < 2; b++)
#pragma unroll
            for (int c = 0; c < 2; c++) { hprev[a][b][c][0] = 0.f; hprev[a][b][c][1] = 0.f; }

#pragma unroll 1
    for (int t = 0; t < NT; t++) {
        const int buf = t & 1, bufn = buf ^ 1;

        float4 xn;
        if (gtid < 32 && t + 1 < NT)
            xn = *(const float4*)(g_x + ((size_t)(t + 1) * NSEQ + seq0 + mg * 32 + gtid) * 4);

        float acc[2][3][2][4];
#pragma unroll
        for (int mt = 0; mt < 2; mt++)
#pragma unroll
            for (int gt = 0; gt < 3; gt++)
#pragma unroll
                for (int sb = 0; sb < 2; sb++)
#pragma unroll
                    for (int r = 0; r < 4; r++) acc[mt][gt][sb][r] = 0.0f;

        // ---- HMMA mainloop: K streamed, B hi/lo per n-tile -----------------
#pragma unroll
        for (int kt = 0; kt < 4; kt++) {
            uint4 ah[2], al[2];
#pragma unroll
            for (int mt = 0; mt < 2; mt++) {
                int mtg = mg * 2 + mt;
                ah[mt] = *(const uint4*)(smem + SO_A + (size_t)(((buf*2 + 0)*4 + mtg)*4 + kt)*512 + l*16);
                al[mt] = *(const uint4*)(smem + SO_A + (size_t)(((buf*2 + 1)*4 + mtg)*4 + kt)*512 + l*16);
            }
#pragma unroll
            for (int gt = 0; gt < 3; gt++)
#pragma unroll
            for (int sb = 0; sb < 2; sb++) {
                int ntile = gt * 8 + ng * 2 + sb;
                uint2 bhi = *(const uint2*)(smem + SO_B + (size_t)(((0*24 + ntile)*4 + kt))*256 + l*8);
                hmma(acc[0][gt][sb], ah[0].x, ah[0].y, ah[0].z, ah[0].w, bhi.x, bhi.y);
                hmma(acc[1][gt][sb], ah[1].x, ah[1].y, ah[1].z, ah[1].w, bhi.x, bhi.y);
                hmma(acc[0][gt][sb], al[0].x, al[0].y, al[0].z, al[0].w, bhi.x, bhi.y);
                hmma(acc[1][gt][sb], al[1].x, al[1].y, al[1].z, al[1].w, bhi.x, bhi.y);
                uint2 blo = *(const uint2*)(smem + SO_B + (size_t)(((1*24 + ntile)*4 + kt))*256 + l*8);
                hmma(acc[0][gt][sb], ah[0].x, ah[0].y, ah[0].z, ah[0].w, blo.x, blo.y);
                hmma(acc[1][gt][sb], ah[1].x, ah[1].y, ah[1].z, ah[1].w, blo.x, blo.y);
            }
        }

        // ---- epilogue: gates + h update + write bf16 hi/lo A frags ---------
#pragma unroll
        for (int sb = 0; sb < 2; sb++) {
            const int j0 = ng * 16 + sb * 8 + 2 * c4;
            const float4* wt0 = (const float4*)(smem + SO_WT + (size_t)j0 * 64);
            const float4* wt1 = (const float4*)(smem + SO_WT + (size_t)(j0 + 1) * 64);
            float4 wr0 = wt0[0], wz0 = wt0[1], wn0 = wt0[2], bb0 = wt0[3];
            float4 wr1 = wt1[0], wz1 = wt1[1], wn1 = wt1[2], bb1 = wt1[3];
#pragma unroll
            for (int mt = 0; mt < 2; mt++)
#pragma unroll
            for (int rh = 0; rh < 2; rh++) {
                const int m = mg * 32 + mt * 16 + rh * 8 + lr;
                float4 xv = *(const float4*)(smem + SO_X + buf * 1024 + m * 16);
                const int rg = rh * 2;
                float h0 = gru_one(acc[mt][0][sb][rg],   acc[mt][1][sb][rg],   acc[mt][2][sb][rg],
                                   xv, wr0, wz0, wn0, bb0.x, bb0.y, bb0.z, bb0.w,
                                   hprev[mt][rh][sb][0]);
                float h1 = gru_one(acc[mt][0][sb][rg+1], acc[mt][1][sb][rg+1], acc[mt][2][sb][rg+1],
                                   xv, wr1, wz1, wn1, bb1.x, bb1.y, bb1.z, bb1.w,
                                   hprev[mt][rh][sb][1]);
                hprev[mt][rh][sb][0] = h0;
                hprev[mt][rh][sb][1] = h1;

                float2 hv; hv.x = h0; hv.y = h1;
                __nv_bfloat162 hi2 = __float22bfloat162_rn(hv);
                float f0 = __bfloat162float(hi2.x), f1 = __bfloat162float(hi2.y);
                float2 lv; lv.x = h0 - f0; lv.y = h1 - f1;
                __nv_bfloat162 lo2 = __float22bfloat162_rn(lv);

                const int mtg = mg * 2 + mt;
                const size_t roff = (size_t)l * 16 + (rh + 2 * sb) * 4;
                *(uint32_t*)(smem + SO_A + (size_t)(((bufn*2 + 0)*4 + mtg)*4 + ng)*512 + roff)
                    = *reinterpret_cast<uint32_t*>(&hi2);
                *(uint32_t*)(smem + SO_A + (size_t)(((bufn*2 + 1)*4 + mtg)*4 + ng)*512 + roff)
                    = *reinterpret_cast<uint32_t*>(&lo2);

                if (t == NT - 1)
                    *(float2*)(&g_hidden[(size_t)(seq0 + m) * NH + j0]) = hv;
            }
        }
        if (gtid < 32 && t + 1 < NT)
            *(float4*)(smem + SO_X + bufn * 1024 + (mg * 32 + gtid) * 16) = xn;
        // per-mg-group barrier: producers == consumers within group
        asm volatile("bar.sync %0, 128;" :: "r"(1 + mg) : "memory");
    }
}

// ---------------------------------------------------------------------------
// Kernel 3: lane MLP + phase competition head. 4 batches per 256-thread block.
// ---------------------------------------------------------------------------
__constant__ int c_PL[8][2] = {{1,3},{0,2},{5,7},{4,6},{0,1},{2,3},{4,5},{6,7}};

__global__ void __launch_bounds__(256)
post_kernel(const float* __restrict__ feat,
            const float* __restrict__ emb_phase,
            const float* __restrict__ Wv,  const float* __restrict__ bv,
            const float* __restrict__ Wl,  const float* __restrict__ bl,
            const float* __restrict__ Wcf, const float* __restrict__ bcf,
            const float* __restrict__ Wcm, const float* __restrict__ bcm,
            const float* __restrict__ Wfin,const float* __restrict__ bfin,
            float* __restrict__ out)
{
    __shared__ float s_hid[4][NL][NH];
    __shared__ float s_lf[4][NL][8];
    __shared__ float s_line[4][NL][16];
    __shared__ float s_pp[4][NL][16];
    __shared__ float s_Wl[16 * 72];
    __shared__ float s_yc[NL * 7 * 20];
    __shared__ float s_val[4][NL][7];

    const int tid = threadIdx.x;
    const int sub = tid >> 6;          // 0..3
    const int st  = tid & 63;
    const int b   = blockIdx.x * 4 + sub;

    for (int i = tid; i < 16 * 72; i += 256) s_Wl[i] = Wl[i];
    for (int i = tid; i < NL * 7 * 20; i += 256) s_yc[i] = g_yc[i];
    for (int i = st; i < NL * NH; i += 64)
        s_hid[sub][i >> 6][i & 63] = g_hidden[(size_t)b * (NL * NH) + i];

    {
        int l = st >> 3, f = st & 7;
        if (f < 4) {
            float vr = feat[b * 16 + 8 + l];
            s_lf[sub][l][f] = sigf(fmaf(vr, Wv[f], bv[f]));
        } else {
            int c = f - 4;
            int pid = (int)feat[b * 16 + l];
            s_lf[sub][l][f] = sigf(emb_phase[pid * 4 + c]);
        }
    }
    __syncthreads();

    for (int i = st; i < NL * 16; i += 64) {
        int l = i >> 4, o = i & 15;
        const float* wrow = &s_Wl[o * 72];
        float v = bl[o];
#pragma unroll
        for (int c = 0; c < 8; c++)  v = fmaf(s_lf[sub][l][c], wrow[c], v);
#pragma unroll
        for (int k = 0; k < NH; k++) v = fmaf(s_hid[sub][l][k], wrow[8 + k], v);
        s_line[sub][l][o] = fmaxf(v, 0.0f);
    }
    __syncthreads();

    for (int i = st; i < NL * 16; i += 64) {
        int p = i >> 4, o = i & 15;
        s_pp[sub][p][o] = s_line[sub][c_PL[p][0]][o] + s_line[sub][c_PL[p][1]][o];
    }
    __syncthreads();

    if (st < 56) {
        int p = st / 7, qi = st % 7;
        int jq = (qi < p) ? qi : qi + 1;

        float xf[20];
#pragma unroll
        for (int o = 0; o < 20; o++) {
            const float* wc = Wcf + o * 32;
            float v = bcf[o];
#pragma unroll
            for (int c = 0; c < 16; c++) v = fmaf(s_pp[sub][p][c],  wc[c],      v);
#pragma unroll
            for (int c = 0; c < 16; c++) v = fmaf(s_pp[sub][jq][c], wc[16 + c], v);
            xf[o] = fmaxf(v, 0.0f) * s_yc[(p * 7 + qi) * 20 + o];
        }
        float val = bfin[0];
#pragma unroll
        for (int o = 0; o < 20; o++) {
            const float* wm = Wcm + o * 20;
            float v = bcm[o];
#pragma unroll
            for (int c = 0; c < 20; c++) v = fmaf(xf[c], wm[c], v);
            val = fmaf(fmaxf(v, 0.0f), Wfin[o], val);
        }
        s_val[sub][p][qi] = val;
    }
    __syncthreads();

    if (st < NL) {
        float acc = 0.0f;
#pragma unroll
        for (int q = 0; q < 7; q++) acc += s_val[sub][st][q];
        out[b * NL + st] = acc;
    }
}

// ---------------------------------------------------------------------------
// Launch
// ---------------------------------------------------------------------------
extern "C" void kernel_launch(void* const* d_in, const int* in_sizes, int n_in,
                              void* d_out, int out_size)
{
    const float* feature  = (const float*)d_in[0];
    const float* history  = (const float*)d_in[1];
    const int*   relation = (const int*)  d_in[2];
    const float* emb_phase= (const float*)d_in[3];
    const float* Wv       = (const float*)d_in[4];
    const float* bv       = (const float*)d_in[5];
    const float* Wh       = (const float*)d_in[6];
    const float* bh       = (const float*)d_in[7];
    const float* Wih      = (const float*)d_in[8];
    const float* Whh      = (const float*)d_in[9];
    const float* bih      = (const float*)d_in[10];
    const float* bhh      = (const float*)d_in[11];
    const float* Wl       = (const float*)d_in[12];
    const float* bl       = (const float*)d_in[13];
    const float* emb_const= (const float*)d_in[14];
    const float* Wcf      = (const float*)d_in[15];
    const float* bcf      = (const float*)d_in[16];
    const float* Wcc      = (const float*)d_in[17];
    const float* bcc      = (const float*)d_in[18];
    const float* Wcm      = (const float*)d_in[19];
    const float* bcm      = (const float*)d_in[20];
    const float* Wfin     = (const float*)d_in[21];
    const float* bfin     = (const float*)d_in[22];
    float* out = (float*)d_out;

    cudaFuncSetAttribute(gru_kernel, cudaFuncAttributeMaxDynamicSharedMemorySize, SMEMSZ);

    build_B<<<(2*24*4*32 + 255) / 256, 256>>>(Whh);
    build_yc<<<(NL*7*20 + 159) / 160, 160>>>(relation, emb_const, Wcc, bcc);
    {
        int total = NB * NT * NL;
        prep_kernel<<<(total + 255) / 256, 256>>>(history, Wh, bh);
    }
    gru_kernel<<<GCTA, GT, SMEMSZ>>>(Wih, bih, bhh);
    post_kernel<<<NB / 4, 256>>>(feature, emb_phase, Wv, bv, Wl, bl,
                                 Wcf, bcf, Wcm, bcm, Wfin, bfin, out);
}

// round 6
// speedup vs baseline: 5.1915x; 1.4869x over previous
#include <cuda_runtime.h>
#include <cuda_bf16.h>
#include <cuda_fp16.h>
#include <stdint.h>
#include <math.h>

#define NB   2048
#define NT   64
#define NL   8
#define NH   64
#define NSEQ (NB*NL)          // 16384
#define RPC  64               // rows per GRU CTA
#define GCTA (NSEQ/RPC)       // 256 CTAs
#define GT   256              // GRU threads per CTA

// ---- SMEM map (bytes) -----------------------------------------------------
// B frags: 128 tiles (24 ntiles x 4 kt + 32 ntiles kt4) x 32 lanes x 16B = 64KB
// A frags: 2 buf x 4 mtg x 5 kt x 512B = 20KB  (fp16 single-split)
#define SO_B    0
#define SO_A    65536
#define SMEMSZ  (65536 + 20480)   // 86016 -> 2 CTAs/SM

// ---- scratch (__device__ globals; allocs forbidden) -----------------------
__device__ float  g_x[NT * NSEQ * 4];      // [t][seq][4]
__device__ float  g_hidden[NSEQ * NH];     // [seq][64]
__device__ uint4  g_B[128 * 32];           // fragment-linear fp16 hi/lo weights
__device__ float  g_yc[NL * 7 * 20];       // batch-invariant relu(ce@Wcc^T+bcc)

__device__ __forceinline__ float sigf(float x) {
    return __fdividef(1.0f, 1.0f + __expf(-x));
}
__device__ __forceinline__ float tanha(float x) {
    float y;
    asm("tanh.approx.f32 %0, %1;" : "=f"(y) : "f"(x));
    return y;
}
__device__ __forceinline__ float siga(float x) {     // sigmoid via tanh, 1 MUFU
    return fmaf(0.5f, tanha(0.5f * x), 0.5f);
}
__device__ __forceinline__ uint32_t h2bits(float a, float b) {
    __half2 h = __floats2half2_rn(a, b);
    return *reinterpret_cast<uint32_t*>(&h);
}

// mma.sync m16n8k16 f16 -> f32 accumulate
__device__ __forceinline__ void hmma(float c[4], const uint4& a,
                                     uint32_t b0, uint32_t b1) {
    asm("mma.sync.aligned.m16n8k16.row.col.f32.f16.f16.f32 "
        "{%0,%1,%2,%3},{%4,%5,%6,%7},{%8,%9},{%0,%1,%2,%3};"
        : "+f"(c[0]), "+f"(c[1]), "+f"(c[2]), "+f"(c[3])
        : "r"(a.x), "r"(a.y), "r"(a.z), "r"(a.w), "r"(b0), "r"(b1));
}

// ---------------------------------------------------------------------------
// Kernel 0: pack weights (fp16 hi/lo) into fragment-linear uint4 tiles.
// Tiles 0..95:  (ntile 0..23 [gates r,z,ghn], kt 0..3)  -> Whh
// Tiles 96..127: kt4 (32 ntiles, gates r,z,ghn,gin)     -> [Wih ; bias]
// Lane frag: {hi(k0,k0+1), hi(k0+8,k0+9), lo(k0,k0+1), lo(k0+8,k0+9)},
//   n = ntile*8 + lane/4, k0 = 2*(lane%4) (+kt*16 for Whh region).
// ---------------------------------------------------------------------------
__device__ __forceinline__ float b4val(int g, int nl, int k,
                                       const float* Wih, const float* bih,
                                       const float* bhh) {
    if (k < 4) {
        if (g == 0) return Wih[nl * 4 + k];
        if (g == 1) return Wih[(64 + nl) * 4 + k];
        if (g == 2) return 0.0f;
        return Wih[(128 + nl) * 4 + k];
    }
    if (k == 4) {
        if (g == 0) return bih[nl] + bhh[nl];
        if (g == 1) return bih[64 + nl] + bhh[64 + nl];
        if (g == 2) return bhh[128 + nl];
        return bih[128 + nl];
    }
    return 0.0f;
}

__global__ void build_B(const float* __restrict__ Wih, const float* __restrict__ Whh,
                        const float* __restrict__ bih, const float* __restrict__ bhh)
{
    int i = blockIdx.x * blockDim.x + threadIdx.x;
    if (i >= 128 * 32) return;
    int lane = i & 31;
    int tile = i >> 5;

    float w[4];
    if (tile < 96) {
        int ntile = tile >> 2, kt = tile & 3;
        int g = ntile >> 3, nb = ntile & 7;
        int row = g * 64 + nb * 8 + (lane >> 2);
        int k0 = kt * 16 + 2 * (lane & 3);
        w[0] = Whh[row * 64 + k0];     w[1] = Whh[row * 64 + k0 + 1];
        w[2] = Whh[row * 64 + k0 + 8]; w[3] = Whh[row * 64 + k0 + 9];
    } else {
        int ntile = tile - 96;
        int g = ntile >> 3, nb = ntile & 7;
        int nl = nb * 8 + (lane >> 2);
        int k0 = 2 * (lane & 3);
        w[0] = b4val(g, nl, k0,     Wih, bih, bhh);
        w[1] = b4val(g, nl, k0 + 1, Wih, bih, bhh);
        w[2] = b4val(g, nl, k0 + 8, Wih, bih, bhh);
        w[3] = b4val(g, nl, k0 + 9, Wih, bih, bhh);
    }
    __half hi[4], lo[4];
#pragma unroll
    for (int q = 0; q < 4; q++) {
        hi[q] = __float2half_rn(w[q]);
        lo[q] = __float2half_rn(w[q] - __half2float(hi[q]));
    }
    uint4 v;
    { __half2 p(hi[0], hi[1]); v.x = *reinterpret_cast<uint32_t*>(&p); }
    { __half2 p(hi[2], hi[3]); v.y = *reinterpret_cast<uint32_t*>(&p); }
    { __half2 p(lo[0], lo[1]); v.z = *reinterpret_cast<uint32_t*>(&p); }
    { __half2 p(lo[2], lo[3]); v.w = *reinterpret_cast<uint32_t*>(&p); }
    g_B[tile * 32 + lane] = v;
}

// Kernel 0b: batch-invariant yc table
__global__ void build_yc(const int* __restrict__ relation,
                         const float* __restrict__ emb_const,
                         const float* __restrict__ Wcc,
                         const float* __restrict__ bcc)
{
    int i = blockIdx.x * blockDim.x + threadIdx.x;
    if (i >= NL * 7 * 20) return;
    int o = i % 20, pq = i / 20;
    int p = pq / 7, q = pq % 7;
    const float* ce = emb_const + relation[p * 7 + q] * 4;
    float v = bcc[o];
#pragma unroll
    for (int c = 0; c < 4; c++) v = fmaf(ce[c], Wcc[o * 4 + c], v);
    g_yc[i] = fmaxf(v, 0.0f);
}

// ---------------------------------------------------------------------------
// Kernel 1: history gather + (3->4) matmul + sigmoid => g_x [t][seq][4]
// ---------------------------------------------------------------------------
__global__ void prep_kernel(const float* __restrict__ hist,
                            const float* __restrict__ Wh,
                            const float* __restrict__ bh)
{
    int idx = blockIdx.x * blockDim.x + threadIdx.x;
    if (idx >= NB * NT * NL) return;
    int l = idx & 7;
    int t = (idx >> 3) & 63;
    int b = idx >> 9;

    const float* hp = hist + (b * NT + t) * 24;
    float h0 = hp[l], h1 = hp[l + 8], h2 = hp[l + 16];

    float* xp = g_x + ((size_t)t * NSEQ + (b * NL + l)) * 4;
#pragma unroll
    for (int o = 0; o < 4; o++) {
        float v = bh[o] + Wh[o*3 + 0]*h0 + Wh[o*3 + 1]*h1 + Wh[o*3 + 2]*h2;
        xp[o] = sigf(v);
    }
}

// ---------------------------------------------------------------------------
// Kernel 2: tensor-core GRU, fp16 A single-split, fp16 B hi/lo (2 products),
// gi + biases folded into K-tile 4. N = 256 = [r|z|ghn|gin].
// CTA = 64 rows, 8 warps (mg 0/1 x ng 0..3), 2 mt per warp.
// ---------------------------------------------------------------------------
__global__ void __launch_bounds__(GT, 2) gru_kernel()
{
    extern __shared__ char smem[];
    const int tid = threadIdx.x;
    const int l   = tid & 31;
    const int wid = tid >> 5;
    const int mg  = wid >> 2;       // 0,1 : 32-row group
    const int ng  = wid & 3;        // 0..3: 16-j block == kt produced
    const int gtid = tid & 127;
    const int c4  = l & 3;
    const int lr  = l >> 2;
    const int seq0 = blockIdx.x * RPC;

    // ---- stage B (64 KB), zero A (20 KB) --------------------------------
    {
        uint4* dst = (uint4*)(smem + SO_B);
#pragma unroll
        for (int i = 0; i < 16; i++) dst[tid + i * GT] = g_B[tid + i * GT];
        uint4 z; z.x = z.y = z.z = z.w = 0u;
        uint4* da = (uint4*)(smem + SO_A);
        for (int i = tid; i < 20480 / 16; i += GT) da[i] = z;
    }
    __syncthreads();
    // stage x(t=0) into buf0 kt4 A-tiles
    if (tid < RPC) {
        float4 xv = *(const float4*)(g_x + (size_t)(seq0 + tid) * 4);
        int mtile = tid >> 4, r = tid & 15;
        char* base = smem + SO_A + (size_t)((0 * 4 + mtile) * 5 + 4) * 512
                   + ((r & 7) * 4) * 16 + (r >> 3) * 4;
        *(uint32_t*)(base)      = h2bits(xv.x, xv.y);
        *(uint32_t*)(base + 16) = h2bits(xv.z, xv.w);
        *(uint32_t*)(base + 32) = h2bits(1.0f, 0.0f);
    }
    __syncthreads();

    float hprev[2][2][2][2];   // [mt][rh][sb][jp]
#pragma unroll
    for (int a = 0; a < 2; a++)
#pragma unroll
        for (int b = 0; b < 2; b++)
#pragma unroll
            for (int c = 0; c < 2; c++) { hprev[a][b][c][0] = 0.f; hprev[a][b][c][1] = 0.f; }

#pragma unroll 1
    for (int t = 0; t < NT; t++) {
        const int buf = t & 1, bufn = buf ^ 1;
        const bool stage = (gtid < 32) && (t + 1 < NT);

        float4 xn;
        if (stage)
            xn = *(const float4*)(g_x + ((size_t)(t + 1) * NSEQ + seq0 + mg * 32 + gtid) * 4);

        float acc[2][4][2][4];
#pragma unroll
        for (int mt = 0; mt < 2; mt++)
#pragma unroll
            for (int gt = 0; gt < 4; gt++)
#pragma unroll
                for (int sb = 0; sb < 2; sb++)
#pragma unroll
                    for (int r = 0; r < 4; r++) acc[mt][gt][sb][r] = 0.0f;

        // ---- HMMA mainloop: kt0-3 (h x Whh), r/z/ghn only ------------------
#pragma unroll
        for (int kt = 0; kt < 4; kt++) {
            uint4 a0 = *(const uint4*)(smem + SO_A + (size_t)(((buf*4) + mg*2 + 0)*5 + kt)*512 + l*16);
            uint4 a1 = *(const uint4*)(smem + SO_A + (size_t)(((buf*4) + mg*2 + 1)*5 + kt)*512 + l*16);
#pragma unroll
            for (int gt = 0; gt < 3; gt++)
#pragma unroll
            for (int sb = 0; sb < 2; sb++) {
                int ntile = gt * 8 + ng * 2 + sb;
                uint4 b = *(const uint4*)(smem + SO_B + (size_t)((ntile*4 + kt)*32 + l)*16);
                hmma(acc[0][gt][sb], a0, b.x, b.y);
                hmma(acc[0][gt][sb], a0, b.z, b.w);
                hmma(acc[1][gt][sb], a1, b.x, b.y);
                hmma(acc[1][gt][sb], a1, b.z, b.w);
            }
        }
        // ---- kt4: x,bias for all 4 gates -----------------------------------
        {
            uint4 a0 = *(const uint4*)(smem + SO_A + (size_t)(((buf*4) + mg*2 + 0)*5 + 4)*512 + l*16);
            uint4 a1 = *(const uint4*)(smem + SO_A + (size_t)(((buf*4) + mg*2 + 1)*5 + 4)*512 + l*16);
#pragma unroll
            for (int gt = 0; gt < 4; gt++)
#pragma unroll
            for (int sb = 0; sb < 2; sb++) {
                int ntile = gt * 8 + ng * 2 + sb;
                uint4 b = *(const uint4*)(smem + SO_B + (size_t)((96 + ntile)*32 + l)*16);
                hmma(acc[0][gt][sb], a0, b.x, b.y);
                hmma(acc[0][gt][sb], a0, b.z, b.w);
                hmma(acc[1][gt][sb], a1, b.x, b.y);
                hmma(acc[1][gt][sb], a1, b.z, b.w);
            }
        }

        // ---- epilogue: pure gate math + fp16 h STS.128 per mt --------------
#pragma unroll
        for (int mt = 0; mt < 2; mt++) {
            uint32_t hw[4];
#pragma unroll
            for (int sb = 0; sb < 2; sb++)
#pragma unroll
            for (int rh = 0; rh < 2; rh++) {
                const int rg = rh * 2;
                float r0 = siga(acc[mt][0][sb][rg]);
                float z0 = siga(acc[mt][1][sb][rg]);
                float c0 = tanha(fmaf(r0, acc[mt][2][sb][rg], acc[mt][3][sb][rg]));
                float h0 = fmaf(z0, hprev[mt][rh][sb][0] - c0, c0);
                float r1 = siga(acc[mt][0][sb][rg+1]);
                float z1 = siga(acc[mt][1][sb][rg+1]);
                float c1 = tanha(fmaf(r1, acc[mt][2][sb][rg+1], acc[mt][3][sb][rg+1]));
                float h1 = fmaf(z1, hprev[mt][rh][sb][1] - c1, c1);
                hprev[mt][rh][sb][0] = h0;
                hprev[mt][rh][sb][1] = h1;
                hw[rh + 2 * sb] = h2bits(h0, h1);

                if (t == NT - 1) {
                    const int m  = mg * 32 + mt * 16 + rh * 8 + lr;
                    const int j0 = ng * 16 + sb * 8 + 2 * c4;
                    float2 hv; hv.x = h0; hv.y = h1;
                    *(float2*)(&g_hidden[(size_t)(seq0 + m) * NH + j0]) = hv;
                }
            }
            uint4 v; v.x = hw[0]; v.y = hw[1]; v.z = hw[2]; v.w = hw[3];
            *(uint4*)(smem + SO_A + (size_t)(((bufn*4) + mg*2 + mt)*5 + ng)*512 + l*16) = v;
        }

        // ---- stage x(t+1) into bufn kt4 ------------------------------------
        if (stage) {
            int m = mg * 32 + gtid;
            int mtile = m >> 4, r = m & 15;
            char* base = smem + SO_A + (size_t)((bufn * 4 + mtile) * 5 + 4) * 512
                       + ((r & 7) * 4) * 16 + (r >> 3) * 4;
            *(uint32_t*)(base)      = h2bits(xn.x, xn.y);
            *(uint32_t*)(base + 16) = h2bits(xn.z, xn.w);
            *(uint32_t*)(base + 32) = h2bits(1.0f, 0.0f);
        }
        // per-mg-group barrier: producers == consumers within group
        asm volatile("bar.sync %0, 128;" :: "r"(1 + mg) : "memory");
    }
}

// ---------------------------------------------------------------------------
// Kernel 3: lane MLP + phase competition head. 4 batches per 256-thread block.
// ---------------------------------------------------------------------------
__constant__ int c_PL[8][2] = {{1,3},{0,2},{5,7},{4,6},{0,1},{2,3},{4,5},{6,7}};

__global__ void __launch_bounds__(256)
post_kernel(const float* __restrict__ feat,
            const float* __restrict__ emb_phase,
            const float* __restrict__ Wv,  const float* __restrict__ bv,
            const float* __restrict__ Wl,  const float* __restrict__ bl,
            const float* __restrict__ Wcf, const float* __restrict__ bcf,
            const float* __restrict__ Wcm, const float* __restrict__ bcm,
            const float* __restrict__ Wfin,const float* __restrict__ bfin,
            float* __restrict__ out)
{
    __shared__ float s_hid[4][NL][NH];
    __shared__ float s_lf[4][NL][8];
    __shared__ float s_line[4][NL][16];
    __shared__ float s_pp[4][NL][16];
    __shared__ float s_Wl[16 * 72];
    __shared__ float s_yc[NL * 7 * 20];
    __shared__ float s_val[4][NL][7];

    const int tid = threadIdx.x;
    const int sub = tid >> 6;          // 0..3
    const int st  = tid & 63;
    const int b   = blockIdx.x * 4 + sub;

    for (int i = tid; i < 16 * 72; i += 256) s_Wl[i] = Wl[i];
    for (int i = tid; i < NL * 7 * 20; i += 256) s_yc[i] = g_yc[i];
    for (int i = st; i < NL * NH; i += 64)
        s_hid[sub][i >> 6][i & 63] = g_hidden[(size_t)b * (NL * NH) + i];

    {
        int l = st >> 3, f = st & 7;
        if (f < 4) {
            float vr = feat[b * 16 + 8 + l];
            s_lf[sub][l][f] = sigf(fmaf(vr, Wv[f], bv[f]));
        } else {
            int c = f - 4;
            int pid = (int)feat[b * 16 + l];
            s_lf[sub][l][f] = sigf(emb_phase[pid * 4 + c]);
        }
    }
    __syncthreads();

    for (int i = st; i < NL * 16; i += 64) {
        int l = i >> 4, o = i & 15;
        const float* wrow = &s_Wl[o * 72];
        float v = bl[o];
#pragma unroll
        for (int c = 0; c < 8; c++)  v = fmaf(s_lf[sub][l][c], wrow[c], v);
#pragma unroll
        for (int k = 0; k < NH; k++) v = fmaf(s_hid[sub][l][k], wrow[8 + k], v);
        s_line[sub][l][o] = fmaxf(v, 0.0f);
    }
    __syncthreads();

    for (int i = st; i < NL * 16; i += 64) {
        int p = i >> 4, o = i & 15;
        s_pp[sub][p][o] = s_line[sub][c_PL[p][0]][o] + s_line[sub][c_PL[p][1]][o];
    }
    __syncthreads();

    if (st < 56) {
        int p = st / 7, qi = st % 7;
        int jq = (qi < p) ? qi : qi + 1;

        float xf[20];
#pragma unroll
        for (int o = 0; o < 20; o++) {
            const float* wc = Wcf + o * 32;
            float v = bcf[o];
#pragma unroll
            for (int c = 0; c < 16; c++) v = fmaf(s_pp[sub][p][c],  wc[c],      v);
#pragma unroll
            for (int c = 0; c < 16; c++) v = fmaf(s_pp[sub][jq][c], wc[16 + c], v);
            xf[o] = fmaxf(v, 0.0f) * s_yc[(p * 7 + qi) * 20 + o];
        }
        float val = bfin[0];
#pragma unroll
        for (int o = 0; o < 20; o++) {
            const float* wm = Wcm + o * 20;
            float v = bcm[o];
#pragma unroll
            for (int c = 0; c < 20; c++) v = fmaf(xf[c], wm[c], v);
            val = fmaf(fmaxf(v, 0.0f), Wfin[o], val);
        }
        s_val[sub][p][qi] = val;
    }
    __syncthreads();

    if (st < NL) {
        float acc = 0.0f;
#pragma unroll
        for (int q = 0; q < 7; q++) acc += s_val[sub][st][q];
        out[b * NL + st] = acc;
    }
}

// ---------------------------------------------------------------------------
// Launch
// ---------------------------------------------------------------------------
extern "C" void kernel_launch(void* const* d_in, const int* in_sizes, int n_in,
                              void* d_out, int out_size)
{
    const float* feature  = (const float*)d_in[0];
    const float* history  = (const float*)d_in[1];
    const int*   relation = (const int*)  d_in[2];
    const float* emb_phase= (const float*)d_in[3];
    const float* Wv       = (const float*)d_in[4];
    const float* bv       = (const float*)d_in[5];
    const float* Wh       = (const float*)d_in[6];
    const float* bh       = (const float*)d_in[7];
    const float* Wih      = (const float*)d_in[8];
    const float* Whh      = (const float*)d_in[9];
    const float* bih      = (const float*)d_in[10];
    const float* bhh      = (const float*)d_in[11];
    const float* Wl       = (const float*)d_in[12];
    const float* bl       = (const float*)d_in[13];
    const float* emb_const= (const float*)d_in[14];
    const float* Wcf      = (const float*)d_in[15];
    const float* bcf      = (const float*)d_in[16];
    const float* Wcc      = (const float*)d_in[17];
    const float* bcc      = (const float*)d_in[18];
    const float* Wcm      = (const float*)d_in[19];
    const float* bcm      = (const float*)d_in[20];
    const float* Wfin     = (const float*)d_in[21];
    const float* bfin     = (const float*)d_in[22];
    float* out = (float*)d_out;

    cudaFuncSetAttribute(gru_kernel, cudaFuncAttributeMaxDynamicSharedMemorySize, SMEMSZ);

    build_B<<<16, 256>>>(Wih, Whh, bih, bhh);
    build_yc<<<(NL*7*20 + 159) / 160, 160>>>(relation, emb_const, Wcc, bcc);
    {
        int total = NB * NT * NL;
        prep_kernel<<<(total + 255) / 256, 256>>>(history, Wh, bh);
    }
    gru_kernel<<<GCTA, GT, SMEMSZ>>>();
    post_kernel<<<NB / 4, 256>>>(feature, emb_phase, Wv, bv, Wl, bl,
                                 Wcf, bcf, Wcm, bcm, Wfin, bfin, out);
}

// round 7
// speedup vs baseline: 6.4624x; 1.2448x over previous
#include <cuda_runtime.h>
#include <cuda_fp16.h>
#include <stdint.h>
#include <math.h>

#define NB   2048
#define NT   64
#define NL   8
#define NH   64
#define NSEQ (NB*NL)          // 16384
#define RPC  64               // rows per GRU CTA
#define GCTA (NSEQ/RPC)       // 256 CTAs
#define GT   256              // GRU threads per CTA

// ---- SMEM map (bytes) -----------------------------------------------------
// B2 : Whh r,z hi-only   : 64 tiles x 256B = 16384
// B4 : Whh ghn hi/lo     : 32 tiles x 512B = 16384
// BK2: kt4 r,z hi-only   : 16 tiles x 256B =  4096
// BK4: kt4 ghn,gin hi/lo : 16 tiles x 512B =  8192
// A  : 2 buf x 4 mtg x 5 kt x 512B = 20480
#define SO_B2   0
#define SO_B4   16384
#define SO_BK2  32768
#define SO_BK4  36864
#define SO_A    45056
#define SMEMSZ  65536

// ---- scratch (__device__ globals; allocs forbidden) -----------------------
__device__ float g_hidden[NSEQ * NH];                 // [seq][64]
__device__ __align__(16) char g_Ball[45056];          // packed B regions
__device__ float g_yc[NL * 7 * 20];                   // relu(ce@Wcc^T+bcc)

__device__ __forceinline__ float sigf(float x) {
    return __fdividef(1.0f, 1.0f + __expf(-x));
}
__device__ __forceinline__ float tanha(float x) {
    float y;
    asm("tanh.approx.f32 %0, %1;" : "=f"(y) : "f"(x));
    return y;
}
__device__ __forceinline__ float siga(float x) {     // sigmoid via tanh, 1 MUFU
    return fmaf(0.5f, tanha(0.5f * x), 0.5f);
}
__device__ __forceinline__ uint32_t h2bits(float a, float b) {
    __half2 h = __floats2half2_rn(a, b);
    return *reinterpret_cast<uint32_t*>(&h);
}

// mma.sync m16n8k16 f16 -> f32 accumulate
__device__ __forceinline__ void hmma(float c[4], const uint4& a,
                                     uint32_t b0, uint32_t b1) {
    asm("mma.sync.aligned.m16n8k16.row.col.f32.f16.f16.f32 "
        "{%0,%1,%2,%3},{%4,%5,%6,%7},{%8,%9},{%0,%1,%2,%3};"
        : "+f"(c[0]), "+f"(c[1]), "+f"(c[2]), "+f"(c[3])
        : "r"(a.x), "r"(a.y), "r"(a.z), "r"(a.w), "r"(b0), "r"(b1));
}

// ---------------------------------------------------------------------------
// Kernel 0: pack weights into fragment-linear regions of g_Ball.
// gates g: 0=r, 1=z, 2=ghn, 3=gin
// ---------------------------------------------------------------------------
__device__ __forceinline__ float b4val(int g, int nl, int k,
                                       const float* Wih, const float* bih,
                                       const float* bhh) {
    if (k < 4) {
        if (g == 0) return Wih[nl * 4 + k];
        if (g == 1) return Wih[(64 + nl) * 4 + k];
        if (g == 2) return 0.0f;
        return Wih[(128 + nl) * 4 + k];
    }
    if (k == 4) {
        if (g == 0) return bih[nl] + bhh[nl];
        if (g == 1) return bih[64 + nl] + bhh[64 + nl];
        if (g == 2) return bhh[128 + nl];
        return bih[128 + nl];
    }
    return 0.0f;
}

__global__ void build_B(const float* __restrict__ Wih, const float* __restrict__ Whh,
                        const float* __restrict__ bih, const float* __restrict__ bhh)
{
    int i = blockIdx.x * blockDim.x + threadIdx.x;
    if (i >= 4096) return;
    int lane = i & 31;
    float w[4];
    char* dst;
    bool wide;

    if (i < 2048) {                       // B2: Whh r,z hi-only
        int tile = i >> 5;                // 0..63 = nt16*4 + kt
        int kt = tile & 3, nt16 = tile >> 2;
        int g = nt16 >> 3, nb = nt16 & 7;
        int row = g * 64 + nb * 8 + (lane >> 2);
        int k0 = kt * 16 + 2 * (lane & 3);
        w[0] = Whh[row*64 + k0];     w[1] = Whh[row*64 + k0 + 1];
        w[2] = Whh[row*64 + k0 + 8]; w[3] = Whh[row*64 + k0 + 9];
        dst = g_Ball + SO_B2 + tile * 256 + lane * 8;  wide = false;
    } else if (i < 3072) {                // B4: Whh ghn hi/lo
        int idx = i - 2048, tile = idx >> 5;   // 0..31 = nt8*4 + kt
        int kt = tile & 3, nt8 = tile >> 2;
        int row = 128 + nt8 * 8 + (lane >> 2);
        int k0 = kt * 16 + 2 * (lane & 3);
        w[0] = Whh[row*64 + k0];     w[1] = Whh[row*64 + k0 + 1];
        w[2] = Whh[row*64 + k0 + 8]; w[3] = Whh[row*64 + k0 + 9];
        dst = g_Ball + SO_B4 + tile * 512 + lane * 16; wide = true;
    } else if (i < 3584) {                // BK2: kt4 r,z hi-only
        int idx = i - 3072, tile = idx >> 5;   // 0..15 = g*8 + nb
        int g = tile >> 3, nb = tile & 7;
        int nl = nb * 8 + (lane >> 2);
        int k0 = 2 * (lane & 3);
        w[0] = b4val(g, nl, k0,     Wih, bih, bhh);
        w[1] = b4val(g, nl, k0 + 1, Wih, bih, bhh);
        w[2] = b4val(g, nl, k0 + 8, Wih, bih, bhh);
        w[3] = b4val(g, nl, k0 + 9, Wih, bih, bhh);
        dst = g_Ball + SO_BK2 + tile * 256 + lane * 8; wide = false;
    } else {                              // BK4: kt4 ghn,gin hi/lo
        int idx = i - 3584, tile = idx >> 5;   // 0..15 = (g-2)*8 + nb
        int g = 2 + (tile >> 3), nb = tile & 7;
        int nl = nb * 8 + (lane >> 2);
        int k0 = 2 * (lane & 3);
        w[0] = b4val(g, nl, k0,     Wih, bih, bhh);
        w[1] = b4val(g, nl, k0 + 1, Wih, bih, bhh);
        w[2] = b4val(g, nl, k0 + 8, Wih, bih, bhh);
        w[3] = b4val(g, nl, k0 + 9, Wih, bih, bhh);
        dst = g_Ball + SO_BK4 + tile * 512 + lane * 16; wide = true;
    }

    __half hi[4], lo[4];
#pragma unroll
    for (int q = 0; q < 4; q++) {
        hi[q] = __float2half_rn(w[q]);
        lo[q] = __float2half_rn(w[q] - __half2float(hi[q]));
    }
    uint2 vh;
    { __half2 p(hi[0], hi[1]); vh.x = *reinterpret_cast<uint32_t*>(&p); }
    { __half2 p(hi[2], hi[3]); vh.y = *reinterpret_cast<uint32_t*>(&p); }
    *(uint2*)dst = vh;
    if (wide) {
        uint2 vl;
        { __half2 p(lo[0], lo[1]); vl.x = *reinterpret_cast<uint32_t*>(&p); }
        { __half2 p(lo[2], lo[3]); vl.y = *reinterpret_cast<uint32_t*>(&p); }
        *(uint2*)(dst + 8) = vl;
    }
}

// Kernel 0b: batch-invariant yc table
__global__ void build_yc(const int* __restrict__ relation,
                         const float* __restrict__ emb_const,
                         const float* __restrict__ Wcc,
                         const float* __restrict__ bcc)
{
    int i = blockIdx.x * blockDim.x + threadIdx.x;
    if (i >= NL * 7 * 20) return;
    int o = i % 20, pq = i / 20;
    int p = pq / 7, q = pq % 7;
    const float* ce = emb_const + relation[p * 7 + q] * 4;
    float v = bcc[o];
#pragma unroll
    for (int c = 0; c < 4; c++) v = fmaf(ce[c], Wcc[o * 4 + c], v);
    g_yc[i] = fmaxf(v, 0.0f);
}

// ---------------------------------------------------------------------------
// Kernel 2: tensor-core GRU, fp16 A single, B hi/lo only on n-path.
// x computed in-kernel from history (prep fused into staging warps).
// ---------------------------------------------------------------------------
__global__ void __launch_bounds__(GT, 2)
gru_kernel(const float* __restrict__ hist,
           const float* __restrict__ Wh,
           const float* __restrict__ bh)
{
    extern __shared__ char smem[];
    __shared__ float sW[16];   // [0..11]=Wh, [12..15]=bh
    const int tid = threadIdx.x;
    const int l   = tid & 31;
    const int wid = tid >> 5;
    const int mg  = wid >> 2;       // 0,1 : 32-row group
    const int ng  = wid & 3;        // 0..3: 16-j block == kt produced
    const int gtid = tid & 127;
    const int c4  = l & 3;
    const int lr  = l >> 2;
    const int seq0 = blockIdx.x * RPC;

    // ---- stage B (44 KB), zero A (20 KB), Wh/bh table --------------------
    {
        const uint4* src = (const uint4*)g_Ball;
        uint4* dst = (uint4*)smem;
        for (int i = tid; i < 45056 / 16; i += GT) dst[i] = src[i];
        uint4 z; z.x = z.y = z.z = z.w = 0u;
        uint4* da = (uint4*)(smem + SO_A);
        for (int i = tid; i < 20480 / 16; i += GT) da[i] = z;
        if (tid < 16) sW[tid] = (tid < 12) ? Wh[tid] : bh[tid - 12];
    }
    __syncthreads();

    // ---- stage x(t=0) into buf0 kt4 A-tiles (computed from history) ------
    if (tid < RPC) {
        int seq = seq0 + tid;
        const float* hp = hist + (size_t)(seq >> 3) * (64 * 24) + (seq & 7);
        float a0v = hp[0], a1v = hp[8], a2v = hp[16];
        float xs[4];
#pragma unroll
        for (int o = 0; o < 4; o++)
            xs[o] = sigf(sW[o*3+0]*a0v + sW[o*3+1]*a1v + sW[o*3+2]*a2v + sW[12+o]);
        int mtile = tid >> 4, r = tid & 15;
        char* base = smem + SO_A + (size_t)((0 * 4 + mtile) * 5 + 4) * 512
                   + ((r & 7) * 4) * 16 + (r >> 3) * 4;
        *(uint32_t*)(base)      = h2bits(xs[0], xs[1]);
        *(uint32_t*)(base + 16) = h2bits(xs[2], xs[3]);
        *(uint32_t*)(base + 32) = h2bits(1.0f, 0.0f);
    }
    __syncthreads();

    // staging threads: per-seq history base pointer (row = mg*32 + gtid)
    const bool is_stager = (gtid < 32);
    const float* hbase = nullptr;
    if (is_stager) {
        int seq = seq0 + mg * 32 + gtid;
        hbase = hist + (size_t)(seq >> 3) * (64 * 24) + (seq & 7);
    }

    float hprev[2][2][2][2];   // [mt][rh][sb][jp]
#pragma unroll
    for (int a = 0; a < 2; a++)
#pragma unroll
        for (int b = 0; b < 2; b++)
#pragma unroll
            for (int c = 0; c < 2; c++) { hprev[a][b][c][0] = 0.f; hprev[a][b][c][1] = 0.f; }

#pragma unroll 1
    for (int t = 0; t < NT; t++) {
        const int buf = t & 1, bufn = buf ^ 1;
        const bool stage = is_stager && (t + 1 < NT);

        // ---- compute x(t+1) from history (hidden behind MMA work) --------
        float xs[4];
        if (stage) {
            const float* hp = hbase + (size_t)(t + 1) * 24;
            float a0v = hp[0], a1v = hp[8], a2v = hp[16];
#pragma unroll
            for (int o = 0; o < 4; o++)
                xs[o] = sigf(sW[o*3+0]*a0v + sW[o*3+1]*a1v + sW[o*3+2]*a2v + sW[12+o]);
        }

        float acc[2][4][2][4];
#pragma unroll
        for (int mt = 0; mt < 2; mt++)
#pragma unroll
            for (int gt = 0; gt < 4; gt++)
#pragma unroll
                for (int sb = 0; sb < 2; sb++)
#pragma unroll
                    for (int r = 0; r < 4; r++) acc[mt][gt][sb][r] = 0.0f;

        // ---- HMMA mainloop: kt0-3 (h x Whh) -------------------------------
#pragma unroll
        for (int kt = 0; kt < 4; kt++) {
            uint4 a0 = *(const uint4*)(smem + SO_A + (size_t)(((buf*4) + mg*2 + 0)*5 + kt)*512 + l*16);
            uint4 a1 = *(const uint4*)(smem + SO_A + (size_t)(((buf*4) + mg*2 + 1)*5 + kt)*512 + l*16);
#pragma unroll
            for (int sb = 0; sb < 2; sb++) {
                // ghn: hi + lo products
                uint4 b4 = *(const uint4*)(smem + SO_B4 + (size_t)(((ng*2+sb)*4 + kt))*512 + l*16);
                hmma(acc[0][2][sb], a0, b4.x, b4.y);
                hmma(acc[0][2][sb], a0, b4.z, b4.w);
                hmma(acc[1][2][sb], a1, b4.x, b4.y);
                hmma(acc[1][2][sb], a1, b4.z, b4.w);
                // r, z: hi only
#pragma unroll
                for (int gt = 0; gt < 2; gt++) {
                    uint2 b2 = *(const uint2*)(smem + SO_B2 + (size_t)(((gt*8 + ng*2+sb)*4 + kt))*256 + l*8);
                    hmma(acc[0][gt][sb], a0, b2.x, b2.y);
                    hmma(acc[1][gt][sb], a1, b2.x, b2.y);
                }
            }
        }
        // ---- kt4: x,bias ---------------------------------------------------
        {
            uint4 a0 = *(const uint4*)(smem + SO_A + (size_t)(((buf*4) + mg*2 + 0)*5 + 4)*512 + l*16);
            uint4 a1 = *(const uint4*)(smem + SO_A + (size_t)(((buf*4) + mg*2 + 1)*5 + 4)*512 + l*16);
#pragma unroll
            for (int sb = 0; sb < 2; sb++) {
#pragma unroll
                for (int gt = 0; gt < 2; gt++) {     // r,z hi-only
                    uint2 b2 = *(const uint2*)(smem + SO_BK2 + (size_t)((gt*8 + ng*2+sb))*256 + l*8);
                    hmma(acc[0][gt][sb], a0, b2.x, b2.y);
                    hmma(acc[1][gt][sb], a1, b2.x, b2.y);
                }
#pragma unroll
                for (int gt = 2; gt < 4; gt++) {     // ghn,gin hi/lo
                    uint4 b4 = *(const uint4*)(smem + SO_BK4 + (size_t)(((gt-2)*8 + ng*2+sb))*512 + l*16);
                    hmma(acc[0][gt][sb], a0, b4.x, b4.y);
                    hmma(acc[0][gt][sb], a0, b4.z, b4.w);
                    hmma(acc[1][gt][sb], a1, b4.x, b4.y);
                    hmma(acc[1][gt][sb], a1, b4.z, b4.w);
                }
            }
        }

        // ---- epilogue: gate math + fp16 h STS.128 per mt --------------------
#pragma unroll
        for (int mt = 0; mt < 2; mt++) {
            uint32_t hw[4];
#pragma unroll
            for (int sb = 0; sb < 2; sb++)
#pragma unroll
            for (int rh = 0; rh < 2; rh++) {
                const int rg = rh * 2;
                float r0 = siga(acc[mt][0][sb][rg]);
                float z0 = siga(acc[mt][1][sb][rg]);
                float c0 = tanha(fmaf(r0, acc[mt][2][sb][rg], acc[mt][3][sb][rg]));
                float h0 = fmaf(z0, hprev[mt][rh][sb][0] - c0, c0);
                float r1 = siga(acc[mt][0][sb][rg+1]);
                float z1 = siga(acc[mt][1][sb][rg+1]);
                float c1 = tanha(fmaf(r1, acc[mt][2][sb][rg+1], acc[mt][3][sb][rg+1]));
                float h1 = fmaf(z1, hprev[mt][rh][sb][1] - c1, c1);
                hprev[mt][rh][sb][0] = h0;
                hprev[mt][rh][sb][1] = h1;
                hw[rh + 2 * sb] = h2bits(h0, h1);

                if (t == NT - 1) {
                    const int m  = mg * 32 + mt * 16 + rh * 8 + lr;
                    const int j0 = ng * 16 + sb * 8 + 2 * c4;
                    float2 hv; hv.x = h0; hv.y = h1;
                    *(float2*)(&g_hidden[(size_t)(seq0 + m) * NH + j0]) = hv;
                }
            }
            uint4 v; v.x = hw[0]; v.y = hw[1]; v.z = hw[2]; v.w = hw[3];
            *(uint4*)(smem + SO_A + (size_t)(((bufn*4) + mg*2 + mt)*5 + ng)*512 + l*16) = v;
        }

        // ---- stage x(t+1) into bufn kt4 -------------------------------------
        if (stage) {
            int m = mg * 32 + gtid;
            int mtile = m >> 4, r = m & 15;
            char* base = smem + SO_A + (size_t)((bufn * 4 + mtile) * 5 + 4) * 512
                       + ((r & 7) * 4) * 16 + (r >> 3) * 4;
            *(uint32_t*)(base)      = h2bits(xs[0], xs[1]);
            *(uint32_t*)(base + 16) = h2bits(xs[2], xs[3]);
            *(uint32_t*)(base + 32) = h2bits(1.0f, 0.0f);
        }
        // per-mg-group barrier: producers == consumers within group
        asm volatile("bar.sync %0, 128;" :: "r"(1 + mg) : "memory");
    }
}

// ---------------------------------------------------------------------------
// Kernel 3: lane MLP + phase competition head. 4 batches per 256-thread block.
// ---------------------------------------------------------------------------
__constant__ int c_PL[8][2] = {{1,3},{0,2},{5,7},{4,6},{0,1},{2,3},{4,5},{6,7}};

__global__ void __launch_bounds__(256)
post_kernel(const float* __restrict__ feat,
            const float* __restrict__ emb_phase,
            const float* __restrict__ Wv,  const float* __restrict__ bv,
            const float* __restrict__ Wl,  const float* __restrict__ bl,
            const float* __restrict__ Wcf, const float* __restrict__ bcf,
            const float* __restrict__ Wcm, const float* __restrict__ bcm,
            const float* __restrict__ Wfin,const float* __restrict__ bfin,
            float* __restrict__ out)
{
    __shared__ float s_hid[4][NL][NH];
    __shared__ float s_lf[4][NL][8];
    __shared__ float s_line[4][NL][16];
    __shared__ float s_pp[4][NL][16];
    __shared__ float s_Wl[16 * 72];
    __shared__ float s_yc[NL * 7 * 20];
    __shared__ float s_val[4][NL][7];

    const int tid = threadIdx.x;
    const int sub = tid >> 6;          // 0..3
    const int st  = tid & 63;
    const int b   = blockIdx.x * 4 + sub;

    for (int i = tid; i < 16 * 72; i += 256) s_Wl[i] = Wl[i];
    for (int i = tid; i < NL * 7 * 20; i += 256) s_yc[i] = g_yc[i];
    for (int i = st; i < NL * NH; i += 64)
        s_hid[sub][i >> 6][i & 63] = g_hidden[(size_t)b * (NL * NH) + i];

    {
        int l = st >> 3, f = st & 7;
        if (f < 4) {
            float vr = feat[b * 16 + 8 + l];
            s_lf[sub][l][f] = sigf(fmaf(vr, Wv[f], bv[f]));
        } else {
            int c = f - 4;
            int pid = (int)feat[b * 16 + l];
            s_lf[sub][l][f] = sigf(emb_phase[pid * 4 + c]);
        }
    }
    __syncthreads();

    for (int i = st; i < NL * 16; i += 64) {
        int l = i >> 4, o = i & 15;
        const float* wrow = &s_Wl[o * 72];
        float v = bl[o];
#pragma unroll
        for (int c = 0; c < 8; c++)  v = fmaf(s_lf[sub][l][c], wrow[c], v);
#pragma unroll
        for (int k = 0; k < NH; k++) v = fmaf(s_hid[sub][l][k], wrow[8 + k], v);
        s_line[sub][l][o] = fmaxf(v, 0.0f);
    }
    __syncthreads();

    for (int i = st; i < NL * 16; i += 64) {
        int p = i >> 4, o = i & 15;
        s_pp[sub][p][o] = s_line[sub][c_PL[p][0]][o] + s_line[sub][c_PL[p][1]][o];
    }
    __syncthreads();

    if (st < 56) {
        int p = st / 7, qi = st % 7;
        int jq = (qi < p) ? qi : qi + 1;

        float xf[20];
#pragma unroll
        for (int o = 0; o < 20; o++) {
            const float* wc = Wcf + o * 32;
            float v = bcf[o];
#pragma unroll
            for (int c = 0; c < 16; c++) v = fmaf(s_pp[sub][p][c],  wc[c],      v);
#pragma unroll
            for (int c = 0; c < 16; c++) v = fmaf(s_pp[sub][jq][c], wc[16 + c], v);
            xf[o] = fmaxf(v, 0.0f) * s_yc[(p * 7 + qi) * 20 + o];
        }
        float val = bfin[0];
#pragma unroll
        for (int o = 0; o < 20; o++) {
            const float* wm = Wcm + o * 20;
            float v = bcm[o];
#pragma unroll
            for (int c = 0; c < 20; c++) v = fmaf(xf[c], wm[c], v);
            val = fmaf(fmaxf(v, 0.0f), Wfin[o], val);
        }
        s_val[sub][p][qi] = val;
    }
    __syncthreads();

    if (st < NL) {
        float acc = 0.0f;
#pragma unroll
        for (int q = 0; q < 7; q++) acc += s_val[sub][st][q];
        out[b * NL + st] = acc;
    }
}

// ---------------------------------------------------------------------------
// Launch
// ---------------------------------------------------------------------------
extern "C" void kernel_launch(void* const* d_in, const int* in_sizes, int n_in,
                              void* d_out, int out_size)
{
    const float* feature  = (const float*)d_in[0];
    const float* history  = (const float*)d_in[1];
    const int*   relation = (const int*)  d_in[2];
    const float* emb_phase= (const float*)d_in[3];
    const float* Wv       = (const float*)d_in[4];
    const float* bv       = (const float*)d_in[5];
    const float* Wh       = (const float*)d_in[6];
    const float* bh       = (const float*)d_in[7];
    const float* Wih      = (const float*)d_in[8];
    const float* Whh      = (const float*)d_in[9];
    const float* bih      = (const float*)d_in[10];
    const float* bhh      = (const float*)d_in[11];
    const float* Wl       = (const float*)d_in[12];
    const float* bl       = (const float*)d_in[13];
    const float* emb_const= (const float*)d_in[14];
    const float* Wcf      = (const float*)d_in[15];
    const float* bcf      = (const float*)d_in[16];
    const float* Wcc      = (const float*)d_in[17];
    const float* bcc      = (const float*)d_in[18];
    const float* Wcm      = (const float*)d_in[19];
    const float* bcm      = (const float*)d_in[20];
    const float* Wfin     = (const float*)d_in[21];
    const float* bfin     = (const float*)d_in[22];
    float* out = (float*)d_out;

    cudaFuncSetAttribute(gru_kernel, cudaFuncAttributeMaxDynamicSharedMemorySize, SMEMSZ);

    build_B<<<16, 256>>>(Wih, Whh, bih, bhh);
    build_yc<<<(NL*7*20 + 159) / 160, 160>>>(relation, emb_const, Wcc, bcc);
    gru_kernel<<<GCTA, GT, SMEMSZ>>>(history, Wh, bh);
    post_kernel<<<NB / 4, 256>>>(feature, emb_phase, Wv, bv, Wl, bl,
                                 Wcf, bcf, Wcm, bcm, Wfin, bfin, out);
}